// round 2
// baseline (speedup 1.0000x reference)
#include <cuda_runtime.h>
#include <cuda_bf16.h>
#include <math.h>

#define CI 256

// ---------------- device scratch (no allocation allowed) ----------------
__device__ float g_l2[2*256*64*64];
__device__ float g_l3[2*256*32*32];
__device__ float g_t [2*256*64*64];
__device__ float g_f [2*256*64*64];
__device__ float g_wt1[256*9*256];
__device__ float g_wt2[256*9*256];
__device__ float g_wtr[256*9*32];
__device__ float g_b1[256];
__device__ float g_b2[256];
__device__ float g_score[2*12288];
__device__ float g_loc [2*12288*4];
__device__ float g_boxes[2*12288*4];
__device__ float g_sval [2*12288];
__device__ unsigned int g_keys[2*12288];
__device__ int   g_topk[2*256];
__device__ int   g_coords[2*3*32*4];
__device__ int   g_mflag [2*3*32];

// ---------------- buffer selectors (device-side, no symbol-address API) ----
__device__ __forceinline__ const float* sel_inbuf(int s, const float* ext) {
    switch (s) {
        case 0: return g_l2;
        case 1: return g_l3;
        case 2: return g_t;
        case 3: return g_f;
        default: return ext;
    }
}

// ---------------- weight transforms (fold BN, transpose to [ci][k][co]) ----
__global__ void wtrans_head_k(const float* __restrict__ w, const float* __restrict__ g,
                              const float* __restrict__ bb, const float* __restrict__ mm,
                              const float* __restrict__ vv, int wsel)
{
    float* wt   = wsel ? g_wt2 : g_wt1;
    float* bias = wsel ? g_b2  : g_b1;
    int i = blockIdx.x*256 + threadIdx.x;
    if (i < 256) {
        float sc = g[i] / sqrtf(vv[i] + 1e-5f);
        bias[i] = bb[i] - mm[i]*sc;
    }
    if (i >= 256*256*9) return;
    int co = i / 2304;
    int r  = i % 2304;
    int ci = r / 9;
    int k  = r % 9;
    float sc = g[co] / sqrtf(vv[co] + 1e-5f);
    wt[((size_t)ci*9 + k)*256 + co] = w[i] * sc;
}

__global__ void wtrans_rpn_k(const float* __restrict__ clsw, const float* __restrict__ locw)
{
    int i = blockIdx.x*256 + threadIdx.x;   // layout [ci][k][32] == linear i
    if (i >= 256*9*32) return;
    int c32 = i % 32;
    int k   = (i/32) % 9;
    int ci  = i / 288;
    float v = 0.f;
    if (c32 < 3)       v = clsw[((size_t)c32*256 + ci)*9 + k];
    else if (c32 < 15) v = locw[((size_t)(c32-3)*256 + ci)*9 + k];
    g_wtr[i] = v;
}

// ---------------- upsample2x + add ----------------
// small_sel: -1 -> small_ext, 0 -> g_l3 ; out_sel: 0 -> g_l3, 1 -> g_l2
__global__ void upadd_k(const float* __restrict__ big, const float* __restrict__ small_ext,
                        int small_sel, int out_sel, int H, int W)
{
    const float* small = (small_sel == 0) ? g_l3 : small_ext;
    float* outp = (out_sel == 0) ? g_l3 : g_l2;
    int i = blockIdx.x*256 + threadIdx.x;
    int total = 2*256*H*W;
    if (i >= total) return;
    int x = i % W;
    int y = (i / W) % H;
    int bc = i / (W*H);
    outp[i] = big[i] + small[((size_t)bc*(H/2) + (y>>1))*(W/2) + (x>>1)];
}

// ---------------- 3x3 conv, block tile 32co x (8x32)px, 16-ci smem chunks ----------------
// mode 0: BN folded + bias + leaky relu -> g_t (out_sel 0) / g_f (out_sel 1)
// mode 1: RPN 15 ch -> g_score / g_loc
#define CI_C 16
#define ISTR 40
__global__ __launch_bounds__(256, 2)
void conv3x3_k(const float* __restrict__ ext_in, int in_sel, int w_sel, int out_sel,
               int H, int W, int CO, int COpad, int nCoG, int mode)
{
    __shared__ float s_in[CI_C*10*ISTR];
    __shared__ float s_w [CI_C*9*32];
    const float* in   = sel_inbuf(in_sel, ext_in);
    const float* wt   = (w_sel == 0) ? g_wt1 : (w_sel == 1) ? g_wt2 : g_wtr;
    const float* bias = (w_sel == 0) ? g_b1  : g_b2;
    float* out = (out_sel == 0) ? g_t : g_f;

    int tid = threadIdx.x;
    int b   = blockIdx.z / nCoG;
    int co0 = (blockIdx.z % nCoG) * 32;
    int tx  = blockIdx.x * 32;
    int ty  = blockIdx.y * 8;
    int cog = tid >> 6;          // 0..3 : 8-channel subgroup
    int py  = (tid >> 3) & 7;    // row in tile
    int px  = tid & 7;           // interleaved col: owns px+8m

    float acc[8][4];
#pragma unroll
    for (int a = 0; a < 8; a++)
#pragma unroll
        for (int m = 0; m < 4; m++) acc[a][m] = 0.f;

    const float* inb = in + (size_t)b*CI*H*W;

    for (int ci0 = 0; ci0 < CI; ci0 += CI_C) {
        if (ci0) __syncthreads();
        for (int i = tid; i < CI_C*10*34; i += 256) {
            int cc = i / 340;
            int r  = i % 340;
            int yy = r / 34;
            int xx = r % 34;
            int gy = ty + yy - 1;
            int gx = tx + xx - 1;
            float v = 0.f;
            if (gy >= 0 && gy < H && gx >= 0 && gx < W)
                v = inb[((size_t)(ci0+cc)*H + gy)*W + gx];
            s_in[(cc*10 + yy)*ISTR + xx] = v;
        }
        for (int i = tid; i < CI_C*9*32; i += 256) {
            int cc  = i / 288;
            int r   = i % 288;
            int k   = r >> 5;
            int c32 = r & 31;
            s_w[i] = wt[((size_t)(ci0+cc)*9 + k)*COpad + co0 + c32];
        }
        __syncthreads();

#pragma unroll 1
        for (int cc = 0; cc < CI_C; cc++) {
#pragma unroll
            for (int ky = 0; ky < 3; ky++) {
                const float* rowp = &s_in[(cc*10 + py + ky)*ISTR];
                float4 wA[3], wB[3];
#pragma unroll
                for (int kx = 0; kx < 3; kx++) {
                    const float4* wp = (const float4*)&s_w[(cc*9 + ky*3 + kx)*32 + cog*8];
                    wA[kx] = wp[0];
                    wB[kx] = wp[1];
                }
#pragma unroll
                for (int m = 0; m < 4; m++) {
#pragma unroll
                    for (int kx = 0; kx < 3; kx++) {
                        float v = rowp[px + 8*m + kx];
                        acc[0][m] += v * wA[kx].x;
                        acc[1][m] += v * wA[kx].y;
                        acc[2][m] += v * wA[kx].z;
                        acc[3][m] += v * wA[kx].w;
                        acc[4][m] += v * wB[kx].x;
                        acc[5][m] += v * wB[kx].y;
                        acc[6][m] += v * wB[kx].z;
                        acc[7][m] += v * wB[kx].w;
                    }
                }
            }
        }
    }

    int y = ty + py;
    if (y >= H) return;
#pragma unroll
    for (int m = 0; m < 4; m++) {
        int x = tx + px + 8*m;
        if (x >= W) continue;
#pragma unroll
        for (int a = 0; a < 8; a++) {
            int co = co0 + cog*8 + a;
            if (co >= CO) break;
            float vv = acc[a][m];
            if (mode == 0) {
                vv += bias[co];
                vv = (vv >= 0.f) ? vv : 0.01f*vv;
                out[(((size_t)b*CI + co)*H + y)*W + x] = vv;
            } else {
                if (co < 3) {
                    g_score[(size_t)b*H*W*3 + ((size_t)y*W + x)*3 + co] = 1.f/(1.f + expf(-vv));
                } else {
                    int cr = co - 3;
                    g_loc[(size_t)b*H*W*12 + (((size_t)y*W + x)*3 + (cr>>2))*4 + (cr&3)] = vv;
                }
            }
        }
    }
}

// ---------------- decode boxes + validity + sort keys ----------------
__global__ void decode_k(const float* __restrict__ anchors, int N, float stride)
{
    int i = blockIdx.x*256 + threadIdx.x;
    if (i >= 2*N) return;
    int b = i / N;
    int a = i % N;
    float sc = g_score[(size_t)b*N + a];
    float t0 = g_loc[((size_t)b*N + a)*4 + 0];
    float t1 = g_loc[((size_t)b*N + a)*4 + 1];
    float t2 = g_loc[((size_t)b*N + a)*4 + 2];
    float t3 = g_loc[((size_t)b*N + a)*4 + 3];
    float a0 = anchors[(size_t)a*4+0], a1 = anchors[(size_t)a*4+1];
    float a2 = anchors[(size_t)a*4+2], a3 = anchors[(size_t)a*4+3];
    float aw = a2 - a0, ah = a3 - a1;
    float x1 = a0 + t0*aw;
    float y1 = a1 + t1*ah;
    float x2 = x1 + aw*expf(t2);
    float y2 = y1 + ah*expf(t3);
    x1 = fminf(fmaxf(x1, 0.f), 512.f);
    y1 = fminf(fmaxf(y1, 0.f), 512.f);
    x2 = fminf(fmaxf(x2, 0.f), 512.f);
    y2 = fminf(fmaxf(y2, 0.f), 512.f);
    bool valid = (sc > 0.5f) && ((x2 - x1) >= 2.f*stride) && ((y2 - y1) >= 2.f*stride);
    float s = valid ? sc : -1.f;
    size_t o = ((size_t)b*N + a)*4;
    g_boxes[o+0] = x1; g_boxes[o+1] = y1; g_boxes[o+2] = x2; g_boxes[o+3] = y2;
    g_sval[(size_t)b*N + a] = s;
    unsigned int u = __float_as_uint(s);
    u = (u & 0x80000000u) ? ~u : (u | 0x80000000u);
    g_keys[(size_t)b*N + a] = u;
}

// ---------------- exact top-256 (score desc, index asc ties) ----------------
// staged=1: keys staged into dynamic smem (N*4 bytes, launched that way).
// staged=0: operate on g_keys directly in global (L2-resident), suppress in place.
// (decode_k fully rewrites g_keys every replay, so in-place zeroing is replay-safe.)
__global__ void topk_k(int N, int staged)
{
    extern __shared__ unsigned int sk[];
    __shared__ unsigned long long wmax[32];
    int b = blockIdx.x;
    int tid = threadIdx.x;
    unsigned int* keys = staged ? sk : (g_keys + (size_t)b*N);
    if (staged) {
        for (int i = tid; i < N; i += 1024) sk[i] = g_keys[(size_t)b*N + i];
        __syncthreads();
    }
    for (int t = 0; t < 256; t++) {
        unsigned long long best = 0ull;
        for (int i = tid; i < N; i += 1024) {
            unsigned long long k = ((unsigned long long)keys[i] << 32) | (unsigned int)(0xFFFFFFFFu - i);
            if (k > best) best = k;
        }
#pragma unroll
        for (int o = 16; o; o >>= 1) {
            unsigned long long oth = __shfl_down_sync(0xffffffffu, best, o);
            if (oth > best) best = oth;
        }
        if ((tid & 31) == 0) wmax[tid >> 5] = best;
        __syncthreads();
        if (tid < 32) {
            best = wmax[tid];
#pragma unroll
            for (int o = 16; o; o >>= 1) {
                unsigned long long oth = __shfl_down_sync(0xffffffffu, best, o);
                if (oth > best) best = oth;
            }
            if (tid == 0) {
                int idx = (int)(0xFFFFFFFFu - (unsigned int)(best & 0xFFFFFFFFull));
                g_topk[b*256 + t] = idx;
                keys[idx] = 0u;     // suppress (real keys are never 0)
            }
        }
        __syncthreads();
    }
}

// ---------------- greedy NMS + ordering + dets/mask/coords ----------------
__global__ void nms_k(int N, int lvl, int stride, float* __restrict__ dout)
{
    __shared__ float bxs[256][4];
    __shared__ float varea[256];
    __shared__ float vvs[256];
    __shared__ int keep[256];
    __shared__ int ord[32];
    int b = blockIdx.x;
    int j = threadIdx.x;
    int idx = g_topk[b*256 + j];
    float x1 = g_boxes[((size_t)b*N + idx)*4 + 0];
    float y1 = g_boxes[((size_t)b*N + idx)*4 + 1];
    float x2 = g_boxes[((size_t)b*N + idx)*4 + 2];
    float y2 = g_boxes[((size_t)b*N + idx)*4 + 3];
    float v  = g_sval[(size_t)b*N + idx];
    bxs[j][0] = x1; bxs[j][1] = y1; bxs[j][2] = x2; bxs[j][3] = y2;
    vvs[j] = v;
    float areaj = (x2 - x1 + 1.f)*(y2 - y1 + 1.f);
    varea[j] = areaj;
    keep[j] = (v > 0.5f) ? 1 : 0;
    __syncthreads();
    for (int i = 0; i < 255; i++) {
        if (j > i && keep[i] && keep[j]) {
            float xx1 = fmaxf(bxs[i][0], x1);
            float yy1 = fmaxf(bxs[i][1], y1);
            float xx2 = fminf(bxs[i][2], x2);
            float yy2 = fminf(bxs[i][3], y2);
            float iw = fmaxf(0.f, xx2 - xx1 + 1.f);
            float ih = fmaxf(0.f, yy2 - yy1 + 1.f);
            float inter = iw*ih;
            float iou = inter / (varea[i] + areaj - inter);
            if (iou > 0.3f) keep[j] = 0;
        }
        __syncthreads();
    }
    if (j == 0) {
        int c = 0;
        for (int q = 0; q < 256 && c < 32; q++) if (keep[q]) ord[c++] = q;
        for (int q = 0; q < 256 && c < 32; q++) if (!keep[q]) ord[c++] = q;
    }
    __syncthreads();
    if (j < 32) {
        int o = ord[j];
        int m = keep[o];
        int slot = (b*3 + lvl)*32 + j;
        size_t dbase = (size_t)slot*5;
        if (m) {
            dout[dbase+0] = bxs[o][0];
            dout[dbase+1] = bxs[o][1];
            dout[dbase+2] = bxs[o][2];
            dout[dbase+3] = bxs[o][3];
            dout[dbase+4] = vvs[o];
        } else {
            dout[dbase+0] = 0.f; dout[dbase+1] = 0.f; dout[dbase+2] = 0.f;
            dout[dbase+3] = 0.f; dout[dbase+4] = 0.f;
        }
        dout[960 + slot] = m ? 1.f : 0.f;
        if (m) {
            g_coords[slot*4+0] = ((int)bxs[o][0]) / stride;
            g_coords[slot*4+1] = ((int)bxs[o][1]) / stride;
            g_coords[slot*4+2] = ((int)bxs[o][2]) / stride;
            g_coords[slot*4+3] = ((int)bxs[o][3]) / stride;
        } else {
            g_coords[slot*4+0] = 0; g_coords[slot*4+1] = 0;
            g_coords[slot*4+2] = 2; g_coords[slot*4+3] = 2;
        }
        g_mflag[slot] = m;
    }
}

// ---------------- ROI adaptive 7x7 max pool (feat = g_f of current level) ----
__global__ void roipool_k(int H, int W, int lvl, float* __restrict__ dout)
{
    int s = blockIdx.x;
    int b = blockIdx.y;
    int c = threadIdx.x;
    int slot = (b*3 + lvl)*32 + s;
    float* dst = dout + 1152 + ((size_t)slot*256 + c)*49;
    int m = g_mflag[slot];
    if (!m) {
#pragma unroll
        for (int k = 0; k < 49; k++) dst[k] = 0.f;
        return;
    }
    int x1 = g_coords[slot*4+0];
    int y1 = g_coords[slot*4+1];
    int x2 = g_coords[slot*4+2];
    int y2 = g_coords[slot*4+3];
    int Lx = x2 - x1;
    int Ly = y2 - y1;
    const float* f = g_f + ((size_t)b*256 + c)*H*W;
    for (int i = 0; i < 7; i++) {
        int ys = y1 + (i*Ly)/7;
        int ye = y1 + ((i+1)*Ly + 6)/7;
        for (int jx = 0; jx < 7; jx++) {
            int xs = x1 + (jx*Lx)/7;
            int xe = x1 + ((jx+1)*Lx + 6)/7;
            float mx = -3.402823466e38f;
            for (int y = ys; y < ye; y++)
                for (int x = xs; x < xe; x++)
                    mx = fmaxf(mx, f[y*W + x]);
            dst[i*7 + jx] = mx;
        }
    }
}

// ---------------- host orchestration (kernel launches ONLY) ----------------
extern "C" void kernel_launch(void* const* d_in, const int* in_sizes, int n_in,
                              void* d_out, int out_size)
{
    const float* layer2   = (const float*)d_in[0];
    const float* layer3   = (const float*)d_in[1];
    const float* layer4   = (const float*)d_in[2];
    const float* anchors2 = (const float*)d_in[3];
    const float* anchors3 = (const float*)d_in[4];
    const float* anchors4 = (const float*)d_in[5];
    const float* hw1 = (const float*)d_in[6];
    const float* hg1 = (const float*)d_in[7];
    const float* hb1 = (const float*)d_in[8];
    const float* hm1 = (const float*)d_in[9];
    const float* hv1 = (const float*)d_in[10];
    const float* hw2 = (const float*)d_in[11];
    const float* hg2 = (const float*)d_in[12];
    const float* hb2 = (const float*)d_in[13];
    const float* hm2 = (const float*)d_in[14];
    const float* hv2 = (const float*)d_in[15];
    const float* clsw = (const float*)d_in[16];
    const float* locw = (const float*)d_in[17];
    float* out = (float*)d_out;

    wtrans_head_k<<<(256*256*9 + 255)/256, 256>>>(hw1, hg1, hb1, hm1, hv1, 0);
    wtrans_head_k<<<(256*256*9 + 255)/256, 256>>>(hw2, hg2, hb2, hm2, hv2, 1);
    wtrans_rpn_k<<<(256*9*32 + 255)/256, 256>>>(clsw, locw);

    upadd_k<<<(2*256*32*32 + 255)/256, 256>>>(layer3, layer4, -1, 0, 32, 32);
    upadd_k<<<(2*256*64*64 + 255)/256, 256>>>(layer2, nullptr, 0, 1, 64, 64);

    struct Lvl { const float* ext; int in_sel; const float* anch; int H, W, N, stride; };
    Lvl lv[3] = {
        { nullptr, 0, anchors2, 64, 64, 12288, 8  },   // g_l2
        { nullptr, 1, anchors3, 32, 32, 3072,  16 },   // g_l3
        { layer4, -1, anchors4, 16, 16, 768,   32 },   // external
    };

    for (int L = 0; L < 3; L++) {
        int H = lv[L].H, W = lv[L].W, N = lv[L].N;
        dim3 gh((W + 31)/32, (H + 7)/8, 2*8);
        conv3x3_k<<<gh, 256>>>(lv[L].ext, lv[L].in_sel, 0, 0, H, W, 256, 256, 8, 0);
        conv3x3_k<<<gh, 256>>>(nullptr,   2,            1, 1, H, W, 256, 256, 8, 0);
        dim3 gr((W + 31)/32, (H + 7)/8, 2);
        conv3x3_k<<<gr, 256>>>(nullptr,   3,            2, 0, H, W, 15, 32, 1, 1);

        decode_k<<<(2*N + 255)/256, 256>>>(lv[L].anch, N, (float)lv[L].stride);

        int staged = (N <= 8192) ? 1 : 0;
        size_t shm = staged ? (size_t)N*4 : 0;
        topk_k<<<2, 1024, shm>>>(N, staged);

        nms_k<<<2, 256>>>(N, L, lv[L].stride, out);
        roipool_k<<<dim3(32, 2), 256>>>(H, W, L, out);
    }
}

// round 3
// speedup vs baseline: 2.0473x; 2.0473x over previous
#include <cuda_runtime.h>
#include <cuda_bf16.h>
#include <math.h>

#define CI 256

// ---------------- device scratch ----------------
// per-level feature offsets (floats): L0: 2*256*64*64, L1: 2*256*32*32, L2: 2*256*16*16
#define TOFF0 0
#define TOFF1 2097152
#define TOFF2 2621440
#define TTOT  2752512
// per-level anchor offsets (elements): N = {12288,3072,768} per image, 2 images
#define AOFF0 0
#define AOFF1 24576
#define AOFF2 30720
#define ATOT  32256

__device__ float g_l2[2*256*64*64];
__device__ float g_l3[2*256*32*32];
__device__ float g_t [TTOT];
__device__ float g_f [TTOT];
__device__ float g_wt1[256*9*256];
__device__ float g_wt2[256*9*256];
__device__ float g_wtr[256*9*32];
__device__ float g_b1[256];
__device__ float g_b2[256];
__device__ float g_score[ATOT];
__device__ float g_loc [ATOT*4];
__device__ float g_boxes[ATOT*4];
__device__ float g_sval [ATOT];
__device__ unsigned int g_keys[ATOT];
__device__ int   g_topk[6*256];
__device__ int   g_coords[2*3*32*4];
__device__ int   g_mflag [2*3*32];

__device__ __forceinline__ int lvlH(int l) { return (l==0)?64:((l==1)?32:16); }
__device__ __forceinline__ int lvlW(int l) { return (l==0)?64:((l==1)?32:16); }
__device__ __forceinline__ int lvlN(int l) { return (l==0)?12288:((l==1)?3072:768); }
__device__ __forceinline__ size_t lvlTOff(int l){ return (l==0)?TOFF0:((l==1)?(size_t)TOFF1:(size_t)TOFF2); }
__device__ __forceinline__ size_t lvlAOff(int l){ return (l==0)?AOFF0:((l==1)?(size_t)AOFF1:(size_t)AOFF2); }
__device__ __forceinline__ int lvlStride(int l){ return 8 << l; }

// ---------------- weight transforms (fold BN, transpose to [ci][k][co]) ----
__global__ void wtrans_head_k(const float* __restrict__ w, const float* __restrict__ g,
                              const float* __restrict__ bb, const float* __restrict__ mm,
                              const float* __restrict__ vv, int wsel)
{
    float* wt   = wsel ? g_wt2 : g_wt1;
    float* bias = wsel ? g_b2  : g_b1;
    int i = blockIdx.x*256 + threadIdx.x;
    if (i < 256) {
        float sc = g[i] / sqrtf(vv[i] + 1e-5f);
        bias[i] = bb[i] - mm[i]*sc;
    }
    if (i >= 256*256*9) return;
    int co = i / 2304;
    int r  = i % 2304;
    int ci = r / 9;
    int k  = r % 9;
    float sc = g[co] / sqrtf(vv[co] + 1e-5f);
    wt[((size_t)ci*9 + k)*256 + co] = w[i] * sc;
}

__global__ void wtrans_rpn_k(const float* __restrict__ clsw, const float* __restrict__ locw)
{
    int i = blockIdx.x*256 + threadIdx.x;   // layout [ci][k][32]
    if (i >= 256*9*32) return;
    int c32 = i % 32;
    int k   = (i/32) % 9;
    int ci  = i / 288;
    float v = 0.f;
    if (c32 < 3)       v = clsw[((size_t)c32*256 + ci)*9 + k];
    else if (c32 < 15) v = locw[((size_t)(c32-3)*256 + ci)*9 + k];
    g_wtr[i] = v;
}

// ---------------- upsample2x + add ----------------
__global__ void upadd_k(const float* __restrict__ big, const float* __restrict__ small_ext,
                        int small_sel, int out_sel, int H, int W)
{
    const float* small = (small_sel == 0) ? g_l3 : small_ext;
    float* outp = (out_sel == 0) ? g_l3 : g_l2;
    int i = blockIdx.x*256 + threadIdx.x;
    int total = 2*256*H*W;
    if (i >= total) return;
    int x = i % W;
    int y = (i / W) % H;
    int bc = i / (W*H);
    outp[i] = big[i] + small[((size_t)bc*(H/2) + (y>>1))*(W/2) + (x>>1)];
}

// ---------------- fused-level 3x3 conv ----------------
// stage 0: conv1 (in: l2/l3/layer4ext -> g_t),  stage 1: conv2 (g_t -> g_f),
// stage 2: rpn   (g_f -> g_score/g_loc, CO=15, COpad=32)
// Linearized blocks: per-level counts passed as boundaries b1,b2.
#define CI_C 16
#define ISTR 40
__global__ __launch_bounds__(256, 2)
void conv3x3_k(const float* __restrict__ ext_in, int stage, int nCoG, int b1v, int b2v)
{
    __shared__ float s_in[CI_C*10*ISTR];
    __shared__ float s_w [CI_C*9*32];

    int bid = blockIdx.x;
    int l, local;
    if (bid < b1v)      { l = 0; local = bid; }
    else if (bid < b2v) { l = 1; local = bid - b1v; }
    else                { l = 2; local = bid - b2v; }

    int H = lvlH(l), W = lvlW(l);
    int xT = (W + 31) >> 5;
    int yT = (H + 7) >> 3;
    int bx = local % xT;
    int by = (local / xT) % yT;
    int bz = local / (xT*yT);
    int b   = bz / nCoG;
    int co0 = (bz % nCoG) * 32;

    const float* in;
    const float* wt;
    const float* bias;
    float* out;
    int CO, COpad, mode;
    if (stage == 0) {
        in = (l==0) ? g_l2 : (l==1) ? g_l3 : ext_in;
        wt = g_wt1; bias = g_b1; out = g_t + lvlTOff(l);
        CO = 256; COpad = 256; mode = 0;
    } else if (stage == 1) {
        in = g_t + lvlTOff(l);
        wt = g_wt2; bias = g_b2; out = g_f + lvlTOff(l);
        CO = 256; COpad = 256; mode = 0;
    } else {
        in = g_f + lvlTOff(l);
        wt = g_wtr; bias = nullptr; out = nullptr;
        CO = 15; COpad = 32; mode = 1;
    }

    int tid = threadIdx.x;
    int tx  = bx * 32;
    int ty  = by * 8;
    int cog = tid >> 6;
    int py  = (tid >> 3) & 7;
    int px  = tid & 7;

    float acc[8][4];
#pragma unroll
    for (int a = 0; a < 8; a++)
#pragma unroll
        for (int m = 0; m < 4; m++) acc[a][m] = 0.f;

    const float* inb = in + (size_t)b*CI*H*W;

    for (int ci0 = 0; ci0 < CI; ci0 += CI_C) {
        if (ci0) __syncthreads();
        for (int i = tid; i < CI_C*10*34; i += 256) {
            int cc = i / 340;
            int r  = i % 340;
            int yy = r / 34;
            int xx = r % 34;
            int gy = ty + yy - 1;
            int gx = tx + xx - 1;
            float v = 0.f;
            if (gy >= 0 && gy < H && gx >= 0 && gx < W)
                v = inb[((size_t)(ci0+cc)*H + gy)*W + gx];
            s_in[(cc*10 + yy)*ISTR + xx] = v;
        }
        for (int i = tid; i < CI_C*9*32; i += 256) {
            int cc  = i / 288;
            int r   = i % 288;
            int k   = r >> 5;
            int c32 = r & 31;
            s_w[i] = wt[((size_t)(ci0+cc)*9 + k)*COpad + co0 + c32];
        }
        __syncthreads();

#pragma unroll 1
        for (int cc = 0; cc < CI_C; cc++) {
#pragma unroll
            for (int ky = 0; ky < 3; ky++) {
                const float* rowp = &s_in[(cc*10 + py + ky)*ISTR];
                float4 wA[3], wB[3];
#pragma unroll
                for (int kx = 0; kx < 3; kx++) {
                    const float4* wp = (const float4*)&s_w[(cc*9 + ky*3 + kx)*32 + cog*8];
                    wA[kx] = wp[0];
                    wB[kx] = wp[1];
                }
#pragma unroll
                for (int m = 0; m < 4; m++) {
#pragma unroll
                    for (int kx = 0; kx < 3; kx++) {
                        float v = rowp[px + 8*m + kx];
                        acc[0][m] += v * wA[kx].x;
                        acc[1][m] += v * wA[kx].y;
                        acc[2][m] += v * wA[kx].z;
                        acc[3][m] += v * wA[kx].w;
                        acc[4][m] += v * wB[kx].x;
                        acc[5][m] += v * wB[kx].y;
                        acc[6][m] += v * wB[kx].z;
                        acc[7][m] += v * wB[kx].w;
                    }
                }
            }
        }
    }

    int y = ty + py;
    if (y >= H) return;
    size_t aoff = lvlAOff(l);
    int N = lvlN(l);
#pragma unroll
    for (int m = 0; m < 4; m++) {
        int x = tx + px + 8*m;
        if (x >= W) continue;
#pragma unroll
        for (int a = 0; a < 8; a++) {
            int co = co0 + cog*8 + a;
            if (co >= CO) break;
            float vv = acc[a][m];
            if (mode == 0) {
                vv += bias[co];
                vv = (vv >= 0.f) ? vv : 0.01f*vv;
                out[(((size_t)b*CI + co)*H + y)*W + x] = vv;
            } else {
                size_t abase = aoff + (size_t)b*N;
                if (co < 3) {
                    g_score[abase + ((size_t)y*W + x)*3 + co] = 1.f/(1.f + expf(-vv));
                } else {
                    int cr = co - 3;
                    g_loc[(abase + ((size_t)y*W + x)*3 + (cr>>2))*4 + (cr&3)] = vv;
                }
            }
        }
    }
}

// ---------------- decode boxes + validity + sort keys (all levels) ----------
__global__ void decode_k(const float* __restrict__ anch0, const float* __restrict__ anch1,
                         const float* __restrict__ anch2)
{
    int gid = blockIdx.x*256 + threadIdx.x;
    if (gid >= ATOT) return;
    int l, r;
    const float* anchors;
    if (gid < AOFF1)      { l = 0; r = gid;         anchors = anch0; }
    else if (gid < AOFF2) { l = 1; r = gid - AOFF1; anchors = anch1; }
    else                  { l = 2; r = gid - AOFF2; anchors = anch2; }
    int N = lvlN(l);
    int a = r % N;
    float stride = (float)lvlStride(l);

    float sc = g_score[gid];
    float t0 = g_loc[(size_t)gid*4 + 0];
    float t1 = g_loc[(size_t)gid*4 + 1];
    float t2 = g_loc[(size_t)gid*4 + 2];
    float t3 = g_loc[(size_t)gid*4 + 3];
    float a0 = anchors[(size_t)a*4+0], a1 = anchors[(size_t)a*4+1];
    float a2 = anchors[(size_t)a*4+2], a3 = anchors[(size_t)a*4+3];
    float aw = a2 - a0, ah = a3 - a1;
    float x1 = a0 + t0*aw;
    float y1 = a1 + t1*ah;
    float x2 = x1 + aw*expf(t2);
    float y2 = y1 + ah*expf(t3);
    x1 = fminf(fmaxf(x1, 0.f), 512.f);
    y1 = fminf(fmaxf(y1, 0.f), 512.f);
    x2 = fminf(fmaxf(x2, 0.f), 512.f);
    y2 = fminf(fmaxf(y2, 0.f), 512.f);
    bool valid = (sc > 0.5f) && ((x2 - x1) >= 2.f*stride) && ((y2 - y1) >= 2.f*stride);
    float s = valid ? sc : -1.f;
    size_t o = (size_t)gid*4;
    g_boxes[o+0] = x1; g_boxes[o+1] = y1; g_boxes[o+2] = x2; g_boxes[o+3] = y2;
    g_sval[gid] = s;
    unsigned int u = __float_as_uint(s);
    u = (u & 0x80000000u) ? ~u : (u | 0x80000000u);
    g_keys[gid] = u;   // never 0
}

// ---------------- exact top-256 via MSB radix select ----------------
// 6 blocks: blk = l*2 + b. Finds T = 256th-largest key, cGT = #keys>T,
// collects >T set (<=255), bitonic sorts by (key desc, idx asc),
// fills remaining (256-cGT) ties by ascending index.
__global__ void topk_k()
{
    __shared__ unsigned int hist[256];
    __shared__ unsigned long long lst[256];
    __shared__ unsigned int wsum[32];
    __shared__ unsigned int sPrefix;
    __shared__ int sK, sCGT, sCnt, sTot, sDone;

    int blk = blockIdx.x;
    int l = blk >> 1;
    int b = blk & 1;
    int N = lvlN(l);
    const unsigned int* keys = g_keys + lvlAOff(l) + (size_t)b*N;
    int tid = threadIdx.x;

    if (tid == 0) { sPrefix = 0u; sK = 256; sCGT = 0; sCnt = 0; sDone = 0; }
    __syncthreads();

    // 4 radix passes, MSB first
    for (int byte = 3; byte >= 0; byte--) {
        for (int i = tid; i < 256; i += 1024) hist[i] = 0u;
        __syncthreads();
        unsigned int pf = sPrefix;
        unsigned int mask = (byte == 3) ? 0u : (0xFFFFFFFFu << ((byte+1)*8));
        for (int i = tid; i < N; i += 1024) {
            unsigned int k = keys[i];
            if ((k & mask) == pf) atomicAdd(&hist[(k >> (byte*8)) & 255], 1u);
        }
        __syncthreads();
        if (tid == 0) {
            int cum = 0;
            int kk = sK;
            int v = 255;
            for (; v >= 0; v--) {
                int c = (int)hist[v];
                if (cum + c >= kk) break;
                cum += c;
            }
            sPrefix |= ((unsigned int)v) << (byte*8);
            sK = kk - cum;
            sCGT += cum;
        }
        __syncthreads();
    }

    unsigned int T = sPrefix;
    int need = sK;          // ties needed (1..256)
    int cg = sCGT;          // count strictly greater (0..255)

    // collect keys > T
    for (int i = tid; i < N; i += 1024) {
        unsigned int k = keys[i];
        if (k > T) {
            int p = atomicAdd(&sCnt, 1);
            lst[p] = ((unsigned long long)k << 32) | (unsigned int)(0xFFFFFFFFu - i);
        }
    }
    __syncthreads();
    if (tid < 256 && tid >= cg) lst[tid] = 0ull;
    __syncthreads();

    // bitonic sort 256 descending
    for (int k = 2; k <= 256; k <<= 1) {
        for (int j = k >> 1; j > 0; j >>= 1) {
            if (tid < 256) {
                int ixj = tid ^ j;
                if (ixj > tid) {
                    bool desc = ((tid & k) == 0);
                    unsigned long long A = lst[tid], Bv = lst[ixj];
                    bool sw = desc ? (A < Bv) : (A > Bv);
                    if (sw) { lst[tid] = Bv; lst[ixj] = A; }
                }
            }
            __syncthreads();
        }
    }

    if (tid < cg)
        g_topk[blk*256 + tid] = (int)(0xFFFFFFFFu - (unsigned int)(lst[tid] & 0xFFFFFFFFull));

    // tie fill: smallest indices with key == T, ascending
    for (int base = 0; base < N; base += 1024) {
        __syncthreads();
        if (sDone >= need) break;
        int i = base + tid;
        int flag = (i < N) && (keys[i] == T);
        unsigned int m = __ballot_sync(0xffffffffu, flag);
        int lane = tid & 31, wd = tid >> 5;
        int laneoff = __popc(m & ((1u << lane) - 1u));
        if (lane == 0) wsum[wd] = __popc(m);
        __syncthreads();
        if (tid == 0) {
            int run = 0;
            for (int w = 0; w < 32; w++) { int c = (int)wsum[w]; wsum[w] = run; run += c; }
            sTot = run;
        }
        __syncthreads();
        if (flag) {
            int pos = sDone + (int)wsum[wd] + laneoff;
            if (pos < need) g_topk[blk*256 + cg + pos] = i;
        }
        __syncthreads();
        if (tid == 0) sDone += sTot;
    }
}

// ---------------- greedy NMS + ordering + dets/mask/coords (6 blocks) ------
__global__ void nms_k(float* __restrict__ dout)
{
    __shared__ float bxs[256][4];
    __shared__ float varea[256];
    __shared__ float vvs[256];
    __shared__ int keep[256];
    __shared__ int ord[32];
    int blk = blockIdx.x;
    int lvl = blk >> 1;
    int b = blk & 1;
    int N = lvlN(lvl);
    int stride = lvlStride(lvl);
    size_t abase = lvlAOff(lvl) + (size_t)b*N;
    int j = threadIdx.x;
    int idx = g_topk[blk*256 + j];
    float x1 = g_boxes[(abase + idx)*4 + 0];
    float y1 = g_boxes[(abase + idx)*4 + 1];
    float x2 = g_boxes[(abase + idx)*4 + 2];
    float y2 = g_boxes[(abase + idx)*4 + 3];
    float v  = g_sval[abase + idx];
    bxs[j][0] = x1; bxs[j][1] = y1; bxs[j][2] = x2; bxs[j][3] = y2;
    vvs[j] = v;
    float areaj = (x2 - x1 + 1.f)*(y2 - y1 + 1.f);
    varea[j] = areaj;
    keep[j] = (v > 0.5f) ? 1 : 0;
    __syncthreads();
    for (int i = 0; i < 255; i++) {
        if (j > i && keep[i] && keep[j]) {
            float xx1 = fmaxf(bxs[i][0], x1);
            float yy1 = fmaxf(bxs[i][1], y1);
            float xx2 = fminf(bxs[i][2], x2);
            float yy2 = fminf(bxs[i][3], y2);
            float iw = fmaxf(0.f, xx2 - xx1 + 1.f);
            float ih = fmaxf(0.f, yy2 - yy1 + 1.f);
            float inter = iw*ih;
            float iou = inter / (varea[i] + areaj - inter);
            if (iou > 0.3f) keep[j] = 0;
        }
        __syncthreads();
    }
    if (j == 0) {
        int c = 0;
        for (int q = 0; q < 256 && c < 32; q++) if (keep[q]) ord[c++] = q;
        for (int q = 0; q < 256 && c < 32; q++) if (!keep[q]) ord[c++] = q;
    }
    __syncthreads();
    if (j < 32) {
        int o = ord[j];
        int m = keep[o];
        int slot = (b*3 + lvl)*32 + j;
        size_t dbase = (size_t)slot*5;
        if (m) {
            dout[dbase+0] = bxs[o][0];
            dout[dbase+1] = bxs[o][1];
            dout[dbase+2] = bxs[o][2];
            dout[dbase+3] = bxs[o][3];
            dout[dbase+4] = vvs[o];
        } else {
            dout[dbase+0] = 0.f; dout[dbase+1] = 0.f; dout[dbase+2] = 0.f;
            dout[dbase+3] = 0.f; dout[dbase+4] = 0.f;
        }
        dout[960 + slot] = m ? 1.f : 0.f;
        if (m) {
            g_coords[slot*4+0] = ((int)bxs[o][0]) / stride;
            g_coords[slot*4+1] = ((int)bxs[o][1]) / stride;
            g_coords[slot*4+2] = ((int)bxs[o][2]) / stride;
            g_coords[slot*4+3] = ((int)bxs[o][3]) / stride;
        } else {
            g_coords[slot*4+0] = 0; g_coords[slot*4+1] = 0;
            g_coords[slot*4+2] = 2; g_coords[slot*4+3] = 2;
        }
        g_mflag[slot] = m;
    }
}

// ---------------- ROI adaptive 7x7 max pool (all levels) -------------------
__global__ void roipool_k(float* __restrict__ dout)
{
    int s = blockIdx.x;
    int b = blockIdx.y;
    int lvl = blockIdx.z;
    int c = threadIdx.x;
    int H = lvlH(lvl), W = lvlW(lvl);
    int slot = (b*3 + lvl)*32 + s;
    float* dst = dout + 1152 + ((size_t)slot*256 + c)*49;
    int m = g_mflag[slot];
    if (!m) {
#pragma unroll
        for (int k = 0; k < 49; k++) dst[k] = 0.f;
        return;
    }
    int x1 = g_coords[slot*4+0];
    int y1 = g_coords[slot*4+1];
    int x2 = g_coords[slot*4+2];
    int y2 = g_coords[slot*4+3];
    int Lx = x2 - x1;
    int Ly = y2 - y1;
    const float* f = g_f + lvlTOff(lvl) + ((size_t)b*256 + c)*H*W;
    for (int i = 0; i < 7; i++) {
        int ys = y1 + (i*Ly)/7;
        int ye = y1 + ((i+1)*Ly + 6)/7;
        for (int jx = 0; jx < 7; jx++) {
            int xs = x1 + (jx*Lx)/7;
            int xe = x1 + ((jx+1)*Lx + 6)/7;
            float mx = -3.402823466e38f;
            for (int y = ys; y < ye; y++)
                for (int x = xs; x < xe; x++)
                    mx = fmaxf(mx, f[y*W + x]);
            dst[i*7 + jx] = mx;
        }
    }
}

// ---------------- host orchestration (kernel launches ONLY) ----------------
extern "C" void kernel_launch(void* const* d_in, const int* in_sizes, int n_in,
                              void* d_out, int out_size)
{
    const float* layer2   = (const float*)d_in[0];
    const float* layer3   = (const float*)d_in[1];
    const float* layer4   = (const float*)d_in[2];
    const float* anchors2 = (const float*)d_in[3];
    const float* anchors3 = (const float*)d_in[4];
    const float* anchors4 = (const float*)d_in[5];
    const float* hw1 = (const float*)d_in[6];
    const float* hg1 = (const float*)d_in[7];
    const float* hb1 = (const float*)d_in[8];
    const float* hm1 = (const float*)d_in[9];
    const float* hv1 = (const float*)d_in[10];
    const float* hw2 = (const float*)d_in[11];
    const float* hg2 = (const float*)d_in[12];
    const float* hb2 = (const float*)d_in[13];
    const float* hm2 = (const float*)d_in[14];
    const float* hv2 = (const float*)d_in[15];
    const float* clsw = (const float*)d_in[16];
    const float* locw = (const float*)d_in[17];
    float* out = (float*)d_out;

    wtrans_head_k<<<(256*256*9 + 255)/256, 256>>>(hw1, hg1, hb1, hm1, hv1, 0);
    wtrans_head_k<<<(256*256*9 + 255)/256, 256>>>(hw2, hg2, hb2, hm2, hv2, 1);
    wtrans_rpn_k<<<(256*9*32 + 255)/256, 256>>>(clsw, locw);

    upadd_k<<<(2*256*32*32 + 255)/256, 256>>>(layer3, layer4, -1, 0, 32, 32);
    upadd_k<<<(2*256*64*64 + 255)/256, 256>>>(layer2, nullptr, 0, 1, 64, 64);

    // block boundaries per stage (levels: {64x64},{32x32},{16x16})
    // stage 0/1: xT*yT*16 => 2*8*16=256, 1*4*16=64, 1*2*16=32 -> total 352
    // stage 2:   xT*yT*2  => 2*8*2 =32,  1*4*2 =8,  1*2*2 =4  -> total 44
    conv3x3_k<<<352, 256>>>(layer4, 0, 8, 256, 320);
    conv3x3_k<<<352, 256>>>(nullptr, 1, 8, 256, 320);
    conv3x3_k<<<44,  256>>>(nullptr, 2, 1, 32, 40);

    decode_k<<<(ATOT + 255)/256, 256>>>(anchors2, anchors3, anchors4);
    topk_k<<<6, 1024>>>();
    nms_k<<<6, 256>>>(out);
    roipool_k<<<dim3(32, 2, 3), 256>>>(out);
}

// round 5
// speedup vs baseline: 2.7986x; 1.3670x over previous
#include <cuda_runtime.h>
#include <cuda_bf16.h>
#include <math.h>

#define CI 256

// ---------------- layout constants ----------------
#define TOFF0 0
#define TOFF1 2097152
#define TOFF2 2621440
#define TTOT  2752512
#define AOFF0 0
#define AOFF1 24576
#define AOFF2 30720
#define ATOT  32256

// ---------------- device scratch ----------------
__device__ float g_l2[2*256*64*64];
__device__ float g_l3[2*256*32*32];
__device__ float g_t [TTOT];
__device__ float g_f [TTOT];
__device__ float g_w1hi[256*2304];
__device__ float g_w1lo[256*2304];
__device__ float g_w2hi[256*2304];
__device__ float g_w2lo[256*2304];
__device__ float g_xhi[TTOT];
__device__ float g_xlo[TTOT];
__device__ float g_wtr[256*9*16];
__device__ float g_b1[256];
__device__ float g_b2[256];
__device__ float g_score[ATOT];
__device__ float g_loc [ATOT*4];
__device__ float g_boxes[ATOT*4];
__device__ float g_sval [ATOT];
__device__ unsigned int g_keys[ATOT];
__device__ int   g_topk[6*256];
__device__ int   g_coords[2*3*32*4];
__device__ int   g_mflag [2*3*32];

__device__ __forceinline__ int lvlH(int l) { return (l==0)?64:((l==1)?32:16); }
__device__ __forceinline__ int lvlW(int l) { return (l==0)?64:((l==1)?32:16); }
__device__ __forceinline__ int lvlN(int l) { return (l==0)?12288:((l==1)?3072:768); }
__device__ __forceinline__ size_t lvlTOff(int l){ return (l==0)?TOFF0:((l==1)?(size_t)TOFF1:(size_t)TOFF2); }
__device__ __forceinline__ size_t lvlAOff(int l){ return (l==0)?AOFF0:((l==1)?(size_t)AOFF1:(size_t)AOFF2); }
__device__ __forceinline__ int lvlStride(int l){ return 8 << l; }

__device__ __forceinline__ float tf32hi(float x) {
    return __uint_as_float(__float_as_uint(x) & 0xFFFFE000u);
}
__device__ __forceinline__ float to_tf32(float x) {
    unsigned u;
    asm("cvt.rna.tf32.f32 %0, %1;" : "=r"(u) : "f"(x));
    return __uint_as_float(u);
}

// ---------------- cp.async helpers ----------------
__device__ __forceinline__ void cp16(unsigned dst, const void* src) {
    asm volatile("cp.async.ca.shared.global [%0], [%1], 16;" :: "r"(dst), "l"(src));
}
__device__ __forceinline__ void cp4z(unsigned dst, const void* src, int ok) {
    int sz = ok ? 4 : 0;
    asm volatile("cp.async.ca.shared.global [%0], [%1], 4, %2;" :: "r"(dst), "l"(src), "r"(sz));
}
__device__ __forceinline__ void mma_tf32(float* c, const unsigned* a, const unsigned* b) {
    asm volatile(
        "mma.sync.aligned.m16n8k8.row.col.f32.tf32.tf32.f32 "
        "{%0,%1,%2,%3}, {%4,%5,%6,%7}, {%8,%9}, {%0,%1,%2,%3};"
        : "+f"(c[0]), "+f"(c[1]), "+f"(c[2]), "+f"(c[3])
        : "r"(a[0]), "r"(a[1]), "r"(a[2]), "r"(a[3]), "r"(b[0]), "r"(b[1]));
}

// ---------------- weight transform: BN fold + hi/lo split, [co][tap*256+ci] -
__global__ void wtrans_head_k(const float* __restrict__ w, const float* __restrict__ g,
                              const float* __restrict__ bb, const float* __restrict__ mm,
                              const float* __restrict__ vv, int wsel)
{
    float* whi = wsel ? g_w2hi : g_w1hi;
    float* wlo = wsel ? g_w2lo : g_w1lo;
    float* bias = wsel ? g_b2 : g_b1;
    int i = blockIdx.x*256 + threadIdx.x;
    if (i < 256) {
        float sc = g[i] / sqrtf(vv[i] + 1e-5f);
        bias[i] = bb[i] - mm[i]*sc;
    }
    if (i >= 256*2304) return;
    int co = i / 2304;
    int r  = i % 2304;
    int ci = r / 9;
    int k  = r % 9;
    float sc = g[co] / sqrtf(vv[co] + 1e-5f);
    float val = w[i] * sc;
    float hi = tf32hi(val);
    size_t o = (size_t)co*2304 + k*256 + ci;
    whi[o] = hi;
    wlo[o] = to_tf32(val - hi);
}

// ---------------- rpn weights: [ci][k][16] ----------------
__global__ void wtrans_rpn_k(const float* __restrict__ clsw, const float* __restrict__ locw)
{
    int i = blockIdx.x*256 + threadIdx.x;
    if (i >= 256*9*16) return;
    int c16 = i % 16;
    int k   = (i/16) % 9;
    int ci  = i / 144;
    float v = 0.f;
    if (c16 < 3)       v = clsw[((size_t)c16*256 + ci)*9 + k];
    else if (c16 < 15) v = locw[((size_t)(c16-3)*256 + ci)*9 + k];
    g_wtr[i] = v;
}

// ---------------- upsample2x + add ----------------
__global__ void upadd_k(const float* __restrict__ big, const float* __restrict__ small_ext,
                        int small_sel, int out_sel, int H, int W)
{
    const float* small = (small_sel == 0) ? g_l3 : small_ext;
    float* outp = (out_sel == 0) ? g_l3 : g_l2;
    int i = blockIdx.x*256 + threadIdx.x;
    int total = 2*256*H*W;
    if (i >= total) return;
    int x = i % W;
    int y = (i / W) % H;
    int bc = i / (W*H);
    outp[i] = big[i] + small[((size_t)bc*(H/2) + (y>>1))*(W/2) + (x>>1)];
}

// ---------------- hi/lo split of conv inputs ----------------
__global__ void split_k(const float* __restrict__ ext4, int stage)
{
    int i = blockIdx.x*256 + threadIdx.x;
    if (i >= TTOT) return;
    float v;
    if (stage == 0) {
        if (i < TOFF1)      v = g_l2[i];
        else if (i < TOFF2) v = g_l3[i - TOFF1];
        else                v = ext4[i - TOFF2];
    } else {
        v = g_t[i];
    }
    float hi = tf32hi(v);
    g_xhi[i] = hi;
    g_xlo[i] = to_tf32(v - hi);
}

// ---------------- TF32x3 mma.sync implicit-GEMM conv ----------------
// C[128 co][64 px] per block; K = 2304 in 144 chunks of 16 (tap, 16 ci).
// grid = 336: b&1 = co half, b>>1 = 168 px-tiles of 64.
// smem buffer (floats): Ahi[128][20] @0, Alo @2560, Bhi[16][72] @5120, Blo @6272
// two buffers of 7424 floats, cp.async double-buffered.
__global__ void __launch_bounds__(256, 2) convmma_k(int stage)
{
    extern __shared__ float sm[];
    const float* wh  = stage ? g_w2hi : g_w1hi;
    const float* wl  = stage ? g_w2lo : g_w1lo;
    const float* bias = stage ? g_b2 : g_b1;
    float* outbuf = stage ? g_f : g_t;

    int bcol = blockIdx.x & 1;
    int co0 = bcol << 7;
    int pt = blockIdx.x >> 1;
    int l, img, ptile;
    if (pt < 128)      { l = 0; img = pt >> 6; ptile = pt & 63; }
    else if (pt < 160) { int q = pt - 128; l = 1; img = q >> 4; ptile = q & 15; }
    else               { int q = pt - 160; l = 2; img = q >> 2; ptile = q & 3; }
    int H = lvlH(l), W = lvlW(l);
    int HW = H * W;
    int logW = (l == 0) ? 6 : ((l == 1) ? 5 : 4);
    size_t toff = lvlTOff(l);
    int p0 = ptile * 64;

    int tid = threadIdx.x;
    int j  = tid & 63;
    int gq = tid >> 6;
    int p = p0 + j;
    int py = p >> logW;
    int px = p & (W - 1);

    const float* xh = g_xhi + toff + (size_t)img*256*HW;
    const float* xl = g_xlo + toff + (size_t)img*256*HW;

    unsigned smb = (unsigned)__cvta_generic_to_shared(sm);

    auto stage_chunk = [&](int c) {
        int s = c & 1;
        unsigned bb = smb + (unsigned)(s * 7424 * 4);
        int tap = c >> 4;
        int ci0 = (c & 15) << 4;
        // A: weights, 512 float4 per half
#pragma unroll
        for (int t = 0; t < 2; t++) {
            int idx = tid + (t << 8);
            int co = idx >> 2, kq = idx & 3;
            unsigned d = bb + (unsigned)((co*20 + kq*4) * 4);
            size_t go = (size_t)(co0 + co)*2304 + tap*256 + ci0 + kq*4;
            cp16(d,            wh + go);
            cp16(d + 2560*4,   wl + go);
        }
        // B: activations with halo predicate
        int dy = tap/3 - 1, dx = tap%3 - 1;
        int sy = py + dy, sx = px + dx;
        int ok = (sy >= 0) && (sy < H) && (sx >= 0) && (sx < W);
        int sb = sy*W + sx;
#pragma unroll
        for (int q = 0; q < 4; q++) {
            int kl = (gq << 2) + q;
            size_t ga = (size_t)(ci0 + kl)*HW + (ok ? sb : 0);
            unsigned d = bb + (unsigned)((5120 + kl*72 + j) * 4);
            cp4z(d,            xh + ga, ok);
            cp4z(d + 1152*4,   xl + ga, ok);
        }
    };

    stage_chunk(0);
    asm volatile("cp.async.commit_group;" ::: "memory");
    stage_chunk(1);
    asm volatile("cp.async.commit_group;" ::: "memory");

    float acc[2][4][4];
#pragma unroll
    for (int m = 0; m < 2; m++)
#pragma unroll
        for (int n = 0; n < 4; n++)
#pragma unroll
            for (int q = 0; q < 4; q++) acc[m][n][q] = 0.f;

    int lane = tid & 31, wid = tid >> 5;
    int wm = wid & 3, wn = wid >> 2;
    int coL = wm * 32, pxL = wn * 32;
    int lr = lane >> 2, lc = lane & 3;

    for (int c = 0; c < 144; c++) {
        asm volatile("cp.async.wait_group 1;" ::: "memory");
        __syncthreads();
        const unsigned* Ah = (const unsigned*)(sm + (c & 1) * 7424);
        const unsigned* Al = Ah + 2560;
        const unsigned* Bh = Ah + 5120;
        const unsigned* Bl = Ah + 6272;
#pragma unroll
        for (int st = 0; st < 2; st++) {
            int k0 = st * 8;
            unsigned bh[4][2], bl[4][2];
#pragma unroll
            for (int n = 0; n < 4; n++) {
                int pxi = pxL + n*8 + lr;
                bh[n][0] = Bh[(k0 + lc)*72 + pxi];
                bh[n][1] = Bh[(k0 + 4 + lc)*72 + pxi];
                bl[n][0] = Bl[(k0 + lc)*72 + pxi];
                bl[n][1] = Bl[(k0 + 4 + lc)*72 + pxi];
            }
#pragma unroll
            for (int m = 0; m < 2; m++) {
                int row = coL + m*16 + lr;
                unsigned ah[4], al[4];
                ah[0] = Ah[row*20 + k0 + lc];
                ah[1] = Ah[(row+8)*20 + k0 + lc];
                ah[2] = Ah[row*20 + k0 + 4 + lc];
                ah[3] = Ah[(row+8)*20 + k0 + 4 + lc];
                al[0] = Al[row*20 + k0 + lc];
                al[1] = Al[(row+8)*20 + k0 + lc];
                al[2] = Al[row*20 + k0 + 4 + lc];
                al[3] = Al[(row+8)*20 + k0 + 4 + lc];
#pragma unroll
                for (int n = 0; n < 4; n++) {
                    mma_tf32(acc[m][n], ah, bh[n]);
                    mma_tf32(acc[m][n], ah, bl[n]);
                    mma_tf32(acc[m][n], al, bh[n]);
                }
            }
        }
        __syncthreads();
        if (c + 2 < 144) stage_chunk(c + 2);
        asm volatile("cp.async.commit_group;" ::: "memory");
    }

    // epilogue: bias + leaky relu, float2 stores
    float* outp = outbuf + toff + (size_t)img*256*HW;
#pragma unroll
    for (int m = 0; m < 2; m++) {
        int co = co0 + coL + m*16 + lr;
        float b0 = bias[co], b1 = bias[co + 8];
#pragma unroll
        for (int n = 0; n < 4; n++) {
            int pxo = p0 + pxL + n*8 + lc*2;
            float t0 = acc[m][n][0] + b0;
            float t1 = acc[m][n][1] + b0;
            float t2 = acc[m][n][2] + b1;
            float t3 = acc[m][n][3] + b1;
            t0 = (t0 >= 0.f) ? t0 : 0.01f*t0;
            t1 = (t1 >= 0.f) ? t1 : 0.01f*t1;
            t2 = (t2 >= 0.f) ? t2 : 0.01f*t2;
            t3 = (t3 >= 0.f) ? t3 : 0.01f*t3;
            *(float2*)(outp + (size_t)co*HW + pxo)       = make_float2(t0, t1);
            *(float2*)(outp + (size_t)(co+8)*HW + pxo)   = make_float2(t2, t3);
        }
    }
}

// ---------------- RPN conv (FFMA, 32x4 px, 16 co) ----------------
#define CI_C 16
#define RISTR 40
__global__ __launch_bounds__(128, 4)
void conv_rpn_k()
{
    __shared__ float s_in[CI_C*6*RISTR];
    __shared__ float s_w [CI_C*9*16];

    int bid = blockIdx.x;
    int l, local;
    if (bid < 64)      { l = 0; local = bid; }
    else if (bid < 80) { l = 1; local = bid - 64; }
    else               { l = 2; local = bid - 80; }
    int H = lvlH(l), W = lvlW(l);
    int HW = H * W;
    int xT = (W >= 32) ? (W >> 5) : 1;
    int yT = H >> 2;
    int bx = local % xT;
    int by = (local / xT) % yT;
    int img = local / (xT*yT);
    int tx = bx * 32;
    int ty = by * 4;

    int tid = threadIdx.x;
    int px  = tid & 7;
    int py  = (tid >> 3) & 3;
    int cog = tid >> 5;

    const float* inb = g_f + lvlTOff(l) + (size_t)img*256*HW;

    float acc[4][4];
#pragma unroll
    for (int a = 0; a < 4; a++)
#pragma unroll
        for (int m = 0; m < 4; m++) acc[a][m] = 0.f;

    for (int ci0 = 0; ci0 < CI; ci0 += CI_C) {
        if (ci0) __syncthreads();
        for (int i = tid; i < CI_C*6*34; i += 128) {
            int cc = i / 204;
            int r  = i % 204;
            int yy = r / 34;
            int xx = r % 34;
            int gy = ty + yy - 1;
            int gx = tx + xx - 1;
            float v = 0.f;
            if (gy >= 0 && gy < H && gx >= 0 && gx < W)
                v = inb[((size_t)(ci0+cc))*HW + gy*W + gx];
            s_in[(cc*6 + yy)*RISTR + xx] = v;
        }
        for (int i = tid; i < CI_C*9*16; i += 128) {
            int cc = i / 144;
            int r  = i % 144;
            s_w[i] = g_wtr[((size_t)(ci0+cc))*144 + r];
        }
        __syncthreads();

#pragma unroll 1
        for (int cc = 0; cc < CI_C; cc++) {
#pragma unroll
            for (int ky = 0; ky < 3; ky++) {
                const float* rowp = &s_in[(cc*6 + py + ky)*RISTR];
#pragma unroll
                for (int kx = 0; kx < 3; kx++) {
                    float4 w4 = *(const float4*)&s_w[(cc*9 + ky*3 + kx)*16 + cog*4];
#pragma unroll
                    for (int m = 0; m < 4; m++) {
                        float v = rowp[px + 8*m + kx];
                        acc[0][m] += v * w4.x;
                        acc[1][m] += v * w4.y;
                        acc[2][m] += v * w4.z;
                        acc[3][m] += v * w4.w;
                    }
                }
            }
        }
    }

    int y = ty + py;
    size_t abase = lvlAOff(l) + (size_t)img*lvlN(l);
#pragma unroll
    for (int m = 0; m < 4; m++) {
        int x = tx + px + 8*m;
        if (x >= W) continue;
#pragma unroll
        for (int a = 0; a < 4; a++) {
            int co = cog*4 + a;
            if (co >= 15) break;
            float vv = acc[a][m];
            if (co < 3) {
                g_score[abase + ((size_t)y*W + x)*3 + co] = 1.f/(1.f + expf(-vv));
            } else {
                int cr = co - 3;
                g_loc[(abase + ((size_t)y*W + x)*3 + (cr>>2))*4 + (cr&3)] = vv;
            }
        }
    }
}

// ---------------- decode boxes + validity + sort keys (all levels) ----------
__global__ void decode_k(const float* __restrict__ anch0, const float* __restrict__ anch1,
                         const float* __restrict__ anch2)
{
    int gid = blockIdx.x*256 + threadIdx.x;
    if (gid >= ATOT) return;
    int l, r;
    const float* anchors;
    if (gid < AOFF1)      { l = 0; r = gid;         anchors = anch0; }
    else if (gid < AOFF2) { l = 1; r = gid - AOFF1; anchors = anch1; }
    else                  { l = 2; r = gid - AOFF2; anchors = anch2; }
    int N = lvlN(l);
    int a = r % N;
    float stride = (float)lvlStride(l);

    float sc = g_score[gid];
    float t0 = g_loc[(size_t)gid*4 + 0];
    float t1 = g_loc[(size_t)gid*4 + 1];
    float t2 = g_loc[(size_t)gid*4 + 2];
    float t3 = g_loc[(size_t)gid*4 + 3];
    float a0 = anchors[(size_t)a*4+0], a1 = anchors[(size_t)a*4+1];
    float a2 = anchors[(size_t)a*4+2], a3 = anchors[(size_t)a*4+3];
    float aw = a2 - a0, ah = a3 - a1;
    float x1 = a0 + t0*aw;
    float y1 = a1 + t1*ah;
    float x2 = x1 + aw*expf(t2);
    float y2 = y1 + ah*expf(t3);
    x1 = fminf(fmaxf(x1, 0.f), 512.f);
    y1 = fminf(fmaxf(y1, 0.f), 512.f);
    x2 = fminf(fmaxf(x2, 0.f), 512.f);
    y2 = fminf(fmaxf(y2, 0.f), 512.f);
    bool valid = (sc > 0.5f) && ((x2 - x1) >= 2.f*stride) && ((y2 - y1) >= 2.f*stride);
    float s = valid ? sc : -1.f;
    size_t o = (size_t)gid*4;
    g_boxes[o+0] = x1; g_boxes[o+1] = y1; g_boxes[o+2] = x2; g_boxes[o+3] = y2;
    g_sval[gid] = s;
    unsigned int u = __float_as_uint(s);
    u = (u & 0x80000000u) ? ~u : (u | 0x80000000u);
    g_keys[gid] = u;
}

// ---------------- exact top-256 via MSB radix select ----------------
__global__ void topk_k()
{
    __shared__ unsigned int hist[256];
    __shared__ unsigned long long lst[256];
    __shared__ unsigned int wsum[32];
    __shared__ unsigned int sPrefix;
    __shared__ int sK, sCGT, sCnt, sTot, sDone;

    int blk = blockIdx.x;
    int l = blk >> 1;
    int b = blk & 1;
    int N = lvlN(l);
    const unsigned int* keys = g_keys + lvlAOff(l) + (size_t)b*N;
    int tid = threadIdx.x;

    if (tid == 0) { sPrefix = 0u; sK = 256; sCGT = 0; sCnt = 0; sDone = 0; }
    __syncthreads();

    for (int byte = 3; byte >= 0; byte--) {
        for (int i = tid; i < 256; i += 1024) hist[i] = 0u;
        __syncthreads();
        unsigned int pf = sPrefix;
        unsigned int mask = (byte == 3) ? 0u : (0xFFFFFFFFu << ((byte+1)*8));
        for (int i = tid; i < N; i += 1024) {
            unsigned int k = keys[i];
            if ((k & mask) == pf) atomicAdd(&hist[(k >> (byte*8)) & 255], 1u);
        }
        __syncthreads();
        if (tid == 0) {
            int cum = 0;
            int kk = sK;
            int v = 255;
            for (; v >= 0; v--) {
                int c = (int)hist[v];
                if (cum + c >= kk) break;
                cum += c;
            }
            sPrefix |= ((unsigned int)v) << (byte*8);
            sK = kk - cum;
            sCGT += cum;
        }
        __syncthreads();
    }

    unsigned int T = sPrefix;
    int need = sK;
    int cg = sCGT;

    for (int i = tid; i < N; i += 1024) {
        unsigned int k = keys[i];
        if (k > T) {
            int p = atomicAdd(&sCnt, 1);
            lst[p] = ((unsigned long long)k << 32) | (unsigned int)(0xFFFFFFFFu - i);
        }
    }
    __syncthreads();
    if (tid < 256 && tid >= cg) lst[tid] = 0ull;
    __syncthreads();

    for (int k = 2; k <= 256; k <<= 1) {
        for (int j = k >> 1; j > 0; j >>= 1) {
            if (tid < 256) {
                int ixj = tid ^ j;
                if (ixj > tid) {
                    bool desc = ((tid & k) == 0);
                    unsigned long long A = lst[tid], Bv = lst[ixj];
                    bool sw = desc ? (A < Bv) : (A > Bv);
                    if (sw) { lst[tid] = Bv; lst[ixj] = A; }
                }
            }
            __syncthreads();
        }
    }

    if (tid < cg)
        g_topk[blk*256 + tid] = (int)(0xFFFFFFFFu - (unsigned int)(lst[tid] & 0xFFFFFFFFull));

    for (int base = 0; base < N; base += 1024) {
        __syncthreads();
        if (sDone >= need) break;
        int i = base + tid;
        int flag = (i < N) && (keys[i] == T);
        unsigned int m = __ballot_sync(0xffffffffu, flag);
        int lane = tid & 31, wd = tid >> 5;
        int laneoff = __popc(m & ((1u << lane) - 1u));
        if (lane == 0) wsum[wd] = __popc(m);
        __syncthreads();
        if (tid == 0) {
            int run = 0;
            for (int w = 0; w < 32; w++) { int c = (int)wsum[w]; wsum[w] = run; run += c; }
            sTot = run;
        }
        __syncthreads();
        if (flag) {
            int pos = sDone + (int)wsum[wd] + laneoff;
            if (pos < need) g_topk[blk*256 + cg + pos] = i;
        }
        __syncthreads();
        if (tid == 0) sDone += sTot;
    }
}

// ---------------- greedy NMS + ordering + dets/mask/coords ------------------
__global__ void nms_k(float* __restrict__ dout)
{
    __shared__ float bxs[256][4];
    __shared__ float varea[256];
    __shared__ float vvs[256];
    __shared__ int keep[256];
    __shared__ int ord[32];
    int blk = blockIdx.x;
    int lvl = blk >> 1;
    int b = blk & 1;
    int N = lvlN(lvl);
    int stride = lvlStride(lvl);
    size_t abase = lvlAOff(lvl) + (size_t)b*N;
    int j = threadIdx.x;
    int idx = g_topk[blk*256 + j];
    float x1 = g_boxes[(abase + idx)*4 + 0];
    float y1 = g_boxes[(abase + idx)*4 + 1];
    float x2 = g_boxes[(abase + idx)*4 + 2];
    float y2 = g_boxes[(abase + idx)*4 + 3];
    float v  = g_sval[abase + idx];
    bxs[j][0] = x1; bxs[j][1] = y1; bxs[j][2] = x2; bxs[j][3] = y2;
    vvs[j] = v;
    float areaj = (x2 - x1 + 1.f)*(y2 - y1 + 1.f);
    varea[j] = areaj;
    keep[j] = (v > 0.5f) ? 1 : 0;
    __syncthreads();
    for (int i = 0; i < 255; i++) {
        if (j > i && keep[i] && keep[j]) {
            float xx1 = fmaxf(bxs[i][0], x1);
            float yy1 = fmaxf(bxs[i][1], y1);
            float xx2 = fminf(bxs[i][2], x2);
            float yy2 = fminf(bxs[i][3], y2);
            float iw = fmaxf(0.f, xx2 - xx1 + 1.f);
            float ih = fmaxf(0.f, yy2 - yy1 + 1.f);
            float inter = iw*ih;
            float iou = inter / (varea[i] + areaj - inter);
            if (iou > 0.3f) keep[j] = 0;
        }
        __syncthreads();
    }
    if (j == 0) {
        int c = 0;
        for (int q = 0; q < 256 && c < 32; q++) if (keep[q]) ord[c++] = q;
        for (int q = 0; q < 256 && c < 32; q++) if (!keep[q]) ord[c++] = q;
    }
    __syncthreads();
    if (j < 32) {
        int o = ord[j];
        int m = keep[o];
        int slot = (b*3 + lvl)*32 + j;
        size_t dbase = (size_t)slot*5;
        if (m) {
            dout[dbase+0] = bxs[o][0];
            dout[dbase+1] = bxs[o][1];
            dout[dbase+2] = bxs[o][2];
            dout[dbase+3] = bxs[o][3];
            dout[dbase+4] = vvs[o];
        } else {
            dout[dbase+0] = 0.f; dout[dbase+1] = 0.f; dout[dbase+2] = 0.f;
            dout[dbase+3] = 0.f; dout[dbase+4] = 0.f;
        }
        dout[960 + slot] = m ? 1.f : 0.f;
        if (m) {
            g_coords[slot*4+0] = ((int)bxs[o][0]) / stride;
            g_coords[slot*4+1] = ((int)bxs[o][1]) / stride;
            g_coords[slot*4+2] = ((int)bxs[o][2]) / stride;
            g_coords[slot*4+3] = ((int)bxs[o][3]) / stride;
        } else {
            g_coords[slot*4+0] = 0; g_coords[slot*4+1] = 0;
            g_coords[slot*4+2] = 2; g_coords[slot*4+3] = 2;
        }
        g_mflag[slot] = m;
    }
}

// ---------------- ROI adaptive 7x7 max pool ----------------
__global__ void roipool_k(float* __restrict__ dout)
{
    int s = blockIdx.x;
    int b = blockIdx.y;
    int lvl = blockIdx.z;
    int c = threadIdx.x;
    int H = lvlH(lvl), W = lvlW(lvl);
    int slot = (b*3 + lvl)*32 + s;
    float* dst = dout + 1152 + ((size_t)slot*256 + c)*49;
    int m = g_mflag[slot];
    if (!m) {
#pragma unroll
        for (int k = 0; k < 49; k++) dst[k] = 0.f;
        return;
    }
    int x1 = g_coords[slot*4+0];
    int y1 = g_coords[slot*4+1];
    int x2 = g_coords[slot*4+2];
    int y2 = g_coords[slot*4+3];
    int Lx = x2 - x1;
    int Ly = y2 - y1;
    const float* f = g_f + lvlTOff(lvl) + ((size_t)b*256 + c)*H*W;
    for (int i = 0; i < 7; i++) {
        int ys = y1 + (i*Ly)/7;
        int ye = y1 + ((i+1)*Ly + 6)/7;
        for (int jx = 0; jx < 7; jx++) {
            int xs = x1 + (jx*Lx)/7;
            int xe = x1 + ((jx+1)*Lx + 6)/7;
            float mx = -3.402823466e38f;
            for (int y = ys; y < ye; y++)
                for (int x = xs; x < xe; x++)
                    mx = fmaxf(mx, f[y*W + x]);
            dst[i*7 + jx] = mx;
        }
    }
}

// ---------------- host orchestration (kernel launches ONLY) ----------------
#define CONVMMA_SMEM 59392

extern "C" void kernel_launch(void* const* d_in, const int* in_sizes, int n_in,
                              void* d_out, int out_size)
{
    const float* layer2   = (const float*)d_in[0];
    const float* layer3   = (const float*)d_in[1];
    const float* layer4   = (const float*)d_in[2];
    const float* anchors2 = (const float*)d_in[3];
    const float* anchors3 = (const float*)d_in[4];
    const float* anchors4 = (const float*)d_in[5];
    const float* hw1 = (const float*)d_in[6];
    const float* hg1 = (const float*)d_in[7];
    const float* hb1 = (const float*)d_in[8];
    const float* hm1 = (const float*)d_in[9];
    const float* hv1 = (const float*)d_in[10];
    const float* hw2 = (const float*)d_in[11];
    const float* hg2 = (const float*)d_in[12];
    const float* hb2 = (const float*)d_in[13];
    const float* hm2 = (const float*)d_in[14];
    const float* hv2 = (const float*)d_in[15];
    const float* clsw = (const float*)d_in[16];
    const float* locw = (const float*)d_in[17];
    float* out = (float*)d_out;

    cudaFuncSetAttribute(convmma_k, cudaFuncAttributeMaxDynamicSharedMemorySize,
                         CONVMMA_SMEM);

    wtrans_head_k<<<(256*2304 + 255)/256, 256>>>(hw1, hg1, hb1, hm1, hv1, 0);
    wtrans_head_k<<<(256*2304 + 255)/256, 256>>>(hw2, hg2, hb2, hm2, hv2, 1);
    wtrans_rpn_k<<<(256*9*16 + 255)/256, 256>>>(clsw, locw);

    upadd_k<<<(2*256*32*32 + 255)/256, 256>>>(layer3, layer4, -1, 0, 32, 32);
    upadd_k<<<(2*256*64*64 + 255)/256, 256>>>(layer2, nullptr, 0, 1, 64, 64);

    split_k<<<(TTOT + 255)/256, 256>>>(layer4, 0);
    convmma_k<<<336, 256, CONVMMA_SMEM>>>(0);
    split_k<<<(TTOT + 255)/256, 256>>>(nullptr, 1);
    convmma_k<<<336, 256, CONVMMA_SMEM>>>(1);

    conv_rpn_k<<<88, 128>>>();

    decode_k<<<(ATOT + 255)/256, 256>>>(anchors2, anchors3, anchors4);
    topk_k<<<6, 1024>>>();
    nms_k<<<6, 256>>>(out);
    roipool_k<<<dim3(32, 2, 3), 256>>>(out);
}

// round 6
// speedup vs baseline: 4.1664x; 1.4887x over previous
#include <cuda_runtime.h>
#include <cuda_bf16.h>
#include <cuda_fp16.h>
#include <math.h>

#define CI 256

// ---------------- layout constants ----------------
#define TOFF0 0
#define TOFF1 2097152
#define TOFF2 2621440
#define TTOT  2752512
#define AOFF0 0
#define AOFF1 24576
#define AOFF2 30720
#define ATOT  32256

// ---------------- device scratch ----------------
__device__ float g_l2[2*256*64*64];
__device__ float g_l3[2*256*32*32];
__device__ float g_t [TTOT];
__device__ float g_f [TTOT];
__device__ __half2 g_w1h[256*9*128];
__device__ __half2 g_w1l[256*9*128];
__device__ __half2 g_w2h[256*9*128];
__device__ __half2 g_w2l[256*9*128];
__device__ __half2 g_xph[TTOT/2];
__device__ __half2 g_xpl[TTOT/2];
__device__ float g_wtr[256*9*16];
__device__ float g_b1[256];
__device__ float g_b2[256];
__device__ float g_score[ATOT];
__device__ float g_loc [ATOT*4];
__device__ float g_boxes[ATOT*4];
__device__ float g_sval [ATOT];
__device__ unsigned int g_keys[ATOT];
__device__ int   g_topk[6*256];
__device__ int   g_coords[2*3*32*4];
__device__ int   g_mflag [2*3*32];

__device__ __forceinline__ int lvlH(int l) { return (l==0)?64:((l==1)?32:16); }
__device__ __forceinline__ int lvlW(int l) { return (l==0)?64:((l==1)?32:16); }
__device__ __forceinline__ int lvlN(int l) { return (l==0)?12288:((l==1)?3072:768); }
__device__ __forceinline__ size_t lvlTOff(int l){ return (l==0)?TOFF0:((l==1)?(size_t)TOFF1:(size_t)TOFF2); }
__device__ __forceinline__ size_t lvlAOff(int l){ return (l==0)?AOFF0:((l==1)?(size_t)AOFF1:(size_t)AOFF2); }
__device__ __forceinline__ int lvlStride(int l){ return 8 << l; }

// ---------------- cp.async + mma helpers ----------------
__device__ __forceinline__ void cp16(unsigned dst, const void* src) {
    asm volatile("cp.async.ca.shared.global [%0], [%1], 16;" :: "r"(dst), "l"(src));
}
__device__ __forceinline__ void cp4z(unsigned dst, const void* src, int ok) {
    int sz = ok ? 4 : 0;
    asm volatile("cp.async.ca.shared.global [%0], [%1], 4, %2;" :: "r"(dst), "l"(src), "r"(sz));
}
__device__ __forceinline__ void mma_f16(float* c, const unsigned* a, const unsigned* b) {
    asm volatile(
        "mma.sync.aligned.m16n8k16.row.col.f32.f16.f16.f32 "
        "{%0,%1,%2,%3}, {%4,%5,%6,%7}, {%8,%9}, {%0,%1,%2,%3};"
        : "+f"(c[0]), "+f"(c[1]), "+f"(c[2]), "+f"(c[3])
        : "r"(a[0]), "r"(a[1]), "r"(a[2]), "r"(a[3]), "r"(b[0]), "r"(b[1]));
}

// ---------------- weight transform: BN fold + f16 hi/lo, packed half2 -------
// layout: [co][tap][128 cipair]
__global__ void wtrans_head_k(const float* __restrict__ w, const float* __restrict__ g,
                              const float* __restrict__ bb, const float* __restrict__ mm,
                              const float* __restrict__ vv, int wsel)
{
    __half2* wph = wsel ? g_w2h : g_w1h;
    __half2* wpl = wsel ? g_w2l : g_w1l;
    float* bias = wsel ? g_b2 : g_b1;
    int i = blockIdx.x*256 + threadIdx.x;
    if (i < 256) {
        float sc = g[i] / sqrtf(vv[i] + 1e-5f);
        bias[i] = bb[i] - mm[i]*sc;
    }
    if (i >= 256*9*128) return;
    int cp  = i % 128;
    int tap = (i/128) % 9;
    int co  = i / 1152;
    float sc = g[co] / sqrtf(vv[co] + 1e-5f);
    float v0 = w[((size_t)co*256 + 2*cp)*9 + tap] * sc;
    float v1 = w[((size_t)co*256 + 2*cp + 1)*9 + tap] * sc;
    __half h0 = __float2half_rn(v0);
    __half h1 = __float2half_rn(v1);
    __half l0 = __float2half_rn(v0 - __half2float(h0));
    __half l1 = __float2half_rn(v1 - __half2float(h1));
    wph[i] = __halves2half2(h0, h1);
    wpl[i] = __halves2half2(l0, l1);
}

// ---------------- rpn weights: [ci][k][16] ----------------
__global__ void wtrans_rpn_k(const float* __restrict__ clsw, const float* __restrict__ locw)
{
    int i = blockIdx.x*256 + threadIdx.x;
    if (i >= 256*9*16) return;
    int c16 = i % 16;
    int k   = (i/16) % 9;
    int ci  = i / 144;
    float v = 0.f;
    if (c16 < 3)       v = clsw[((size_t)c16*256 + ci)*9 + k];
    else if (c16 < 15) v = locw[((size_t)(c16-3)*256 + ci)*9 + k];
    g_wtr[i] = v;
}

// ---------------- upsample2x + add ----------------
__global__ void upadd_k(const float* __restrict__ big, const float* __restrict__ small_ext,
                        int small_sel, int out_sel, int H, int W)
{
    const float* small = (small_sel == 0) ? g_l3 : small_ext;
    float* outp = (out_sel == 0) ? g_l3 : g_l2;
    int i = blockIdx.x*256 + threadIdx.x;
    int total = 2*256*H*W;
    if (i >= total) return;
    int x = i % W;
    int y = (i / W) % H;
    int bc = i / (W*H);
    outp[i] = big[i] + small[((size_t)bc*(H/2) + (y>>1))*(W/2) + (x>>1)];
}

// ---------------- f16 hi/lo split + ci-pair pack of conv inputs ------------
__global__ void split_k(const float* __restrict__ ext4, int stage)
{
    int gid = blockIdx.x*256 + threadIdx.x;
    if (gid >= TTOT/2) return;
    int l, hwlog;
    size_t offp;
    if (gid < TOFF1/2)      { l = 0; offp = 0;        hwlog = 12; }
    else if (gid < TOFF2/2) { l = 1; offp = TOFF1/2;  hwlog = 10; }
    else                    { l = 2; offp = TOFF2/2;  hwlog = 8; }
    int HW = 1 << hwlog;
    int local = gid - (int)offp;
    int p = local & (HW - 1);
    int plane = local >> hwlog;
    int img = plane >> 7;
    int cp = plane & 127;
    size_t base = ((size_t)(img*256 + 2*cp) << hwlog) + p;
    float v0, v1;
    if (stage == 0) {
        const float* src = (l == 0) ? g_l2 : (l == 1) ? g_l3 : ext4;
        v0 = src[base]; v1 = src[base + HW];
    } else {
        const float* src = g_t + lvlTOff(l);
        v0 = src[base]; v1 = src[base + HW];
    }
    __half h0 = __float2half_rn(v0);
    __half h1 = __float2half_rn(v1);
    __half l0 = __float2half_rn(v0 - __half2float(h0));
    __half l1 = __float2half_rn(v1 - __half2float(h1));
    g_xph[gid] = __halves2half2(h0, h1);
    g_xpl[gid] = __halves2half2(l0, l1);
}

// ---------------- FP16x3 mma.sync implicit-GEMM conv ----------------
// C[128 co][64 px]; K = 2304 in 72 chunks of 32 (one tap, 32 ci).
// smem words (4B = half2 or fp32): Ah[128][20] @0, Al @2560, Bh[16][72] @5120,
// Bl @6272; buffer 7424 words, double-buffered.
__global__ void __launch_bounds__(256, 2) convmma_k(int stage)
{
    extern __shared__ float sm[];
    const __half2* wph = stage ? g_w2h : g_w1h;
    const __half2* wpl = stage ? g_w2l : g_w1l;
    const float* bias = stage ? g_b2 : g_b1;
    float* outbuf = stage ? g_f : g_t;

    int bcol = blockIdx.x & 1;
    int co0 = bcol << 7;
    int pt = blockIdx.x >> 1;
    int l, img, ptile;
    if (pt < 128)      { l = 0; img = pt >> 6; ptile = pt & 63; }
    else if (pt < 160) { int q = pt - 128; l = 1; img = q >> 4; ptile = q & 15; }
    else               { int q = pt - 160; l = 2; img = q >> 2; ptile = q & 3; }
    int H = lvlH(l), W = lvlW(l);
    int HW = H * W;
    int logW = (l == 0) ? 6 : ((l == 1) ? 5 : 4);
    size_t toff = lvlTOff(l);
    size_t toffp = toff >> 1;
    int p0 = ptile * 64;

    int tid = threadIdx.x;
    int j  = tid & 63;
    int gq = tid >> 6;
    int p = p0 + j;
    int py = p >> logW;
    int px = p & (W - 1);

    const __half2* xph = g_xph + toffp + (size_t)img*128*HW;
    const __half2* xpl = g_xpl + toffp + (size_t)img*128*HW;

    unsigned smb = (unsigned)__cvta_generic_to_shared(sm);

    auto stage_chunk = [&](int c) {
        int s = c & 1;
        unsigned bb = smb + (unsigned)(s * 7424 * 4);
        int tap = c >> 3;
        int cp0 = (c & 7) << 4;   // ci pair base (ci0/2), 16 pairs per chunk
        // A: weights, 512 cp16 per hi/lo
#pragma unroll
        for (int t = 0; t < 2; t++) {
            int idx = tid + (t << 8);
            int co = idx >> 2, q = idx & 3;
            unsigned d = bb + (unsigned)(co*80 + q*16);
            size_t go = ((size_t)(co0 + co)*9 + tap)*128 + cp0 + q*4;
            cp16(d,            wph + go);
            cp16(d + 2560*4,   wpl + go);
        }
        // B: activations with halo predicate
        int dy = tap/3 - 1, dx = tap%3 - 1;
        int sy = py + dy, sx = px + dx;
        int ok = (sy >= 0) && (sy < H) && (sx >= 0) && (sx < W);
        int sb = sy*W + sx;
#pragma unroll
        for (int q = 0; q < 4; q++) {
            int kl = (gq << 2) + q;
            size_t ga = (size_t)(cp0 + kl)*HW + (ok ? sb : 0);
            unsigned d = bb + (unsigned)((5120 + kl*72 + j) * 4);
            cp4z(d,            xph + ga, ok);
            cp4z(d + 1152*4,   xpl + ga, ok);
        }
    };

    stage_chunk(0);
    asm volatile("cp.async.commit_group;" ::: "memory");
    stage_chunk(1);
    asm volatile("cp.async.commit_group;" ::: "memory");

    float acc[2][4][4];
#pragma unroll
    for (int m = 0; m < 2; m++)
#pragma unroll
        for (int n = 0; n < 4; n++)
#pragma unroll
            for (int q = 0; q < 4; q++) acc[m][n][q] = 0.f;

    int lane = tid & 31, wid = tid >> 5;
    int wm = wid & 3, wn = wid >> 2;
    int coL = wm * 32, pxL = wn * 32;
    int lr = lane >> 2, lc = lane & 3;

    for (int c = 0; c < 72; c++) {
        asm volatile("cp.async.wait_group 1;" ::: "memory");
        __syncthreads();
        const unsigned* Ah = (const unsigned*)(sm + (c & 1) * 7424);
        const unsigned* Al = Ah + 2560;
        const unsigned* Bh = Ah + 5120;
        const unsigned* Bl = Ah + 6272;
#pragma unroll
        for (int st = 0; st < 2; st++) {
            int kb = st * 8;   // kpair base for this k16 step
            unsigned bh[4][2], bl[4][2];
#pragma unroll
            for (int n = 0; n < 4; n++) {
                int pxi = pxL + n*8 + lr;
                bh[n][0] = Bh[(kb + lc)*72 + pxi];
                bh[n][1] = Bh[(kb + 4 + lc)*72 + pxi];
                bl[n][0] = Bl[(kb + lc)*72 + pxi];
                bl[n][1] = Bl[(kb + 4 + lc)*72 + pxi];
            }
#pragma unroll
            for (int m = 0; m < 2; m++) {
                int row = coL + m*16 + lr;
                unsigned ah[4], al[4];
                ah[0] = Ah[row*20 + kb + lc];
                ah[1] = Ah[(row+8)*20 + kb + lc];
                ah[2] = Ah[row*20 + kb + 4 + lc];
                ah[3] = Ah[(row+8)*20 + kb + 4 + lc];
                al[0] = Al[row*20 + kb + lc];
                al[1] = Al[(row+8)*20 + kb + lc];
                al[2] = Al[row*20 + kb + 4 + lc];
                al[3] = Al[(row+8)*20 + kb + 4 + lc];
#pragma unroll
                for (int n = 0; n < 4; n++) {
                    mma_f16(acc[m][n], ah, bh[n]);
                    mma_f16(acc[m][n], ah, bl[n]);
                    mma_f16(acc[m][n], al, bh[n]);
                }
            }
        }
        __syncthreads();
        if (c + 2 < 72) stage_chunk(c + 2);
        asm volatile("cp.async.commit_group;" ::: "memory");
    }

    // epilogue: bias + leaky relu, float2 stores
    float* outp = outbuf + toff + (size_t)img*256*HW;
#pragma unroll
    for (int m = 0; m < 2; m++) {
        int co = co0 + coL + m*16 + lr;
        float b0 = bias[co], b1 = bias[co + 8];
#pragma unroll
        for (int n = 0; n < 4; n++) {
            int pxo = p0 + pxL + n*8 + lc*2;
            float t0 = acc[m][n][0] + b0;
            float t1 = acc[m][n][1] + b0;
            float t2 = acc[m][n][2] + b1;
            float t3 = acc[m][n][3] + b1;
            t0 = (t0 >= 0.f) ? t0 : 0.01f*t0;
            t1 = (t1 >= 0.f) ? t1 : 0.01f*t1;
            t2 = (t2 >= 0.f) ? t2 : 0.01f*t2;
            t3 = (t3 >= 0.f) ? t3 : 0.01f*t3;
            *(float2*)(outp + (size_t)co*HW + pxo)       = make_float2(t0, t1);
            *(float2*)(outp + (size_t)(co+8)*HW + pxo)   = make_float2(t2, t3);
        }
    }
}

// ---------------- RPN conv (FFMA, 32x2 px, 16 co, 176 blocks) ---------------
#define CI_C 16
#define RISTR 40
__global__ __launch_bounds__(128, 4)
void conv_rpn_k()
{
    __shared__ float s_in[CI_C*4*RISTR];
    __shared__ float s_w [CI_C*9*16];

    int bid = blockIdx.x;
    int l, bx, by, img;
    if (bid < 128)      { l = 0; bx = bid & 1; by = (bid >> 1) & 31; img = bid >> 6; }
    else if (bid < 160) { int q = bid - 128; l = 1; bx = 0; by = q & 15; img = q >> 4; }
    else                { int q = bid - 160; l = 2; bx = 0; by = q & 7;  img = q >> 3; }
    int H = lvlH(l), W = lvlW(l);
    int HW = H * W;
    int tx = bx * 32;
    int ty = by * 2;

    int tid = threadIdx.x;
    int px  = tid & 7;
    int py  = (tid >> 3) & 1;
    int cog = tid >> 4;   // 0..7 groups of 2 co

    const float* inb = g_f + lvlTOff(l) + (size_t)img*256*HW;

    float acc[2][4];
#pragma unroll
    for (int a = 0; a < 2; a++)
#pragma unroll
        for (int m = 0; m < 4; m++) acc[a][m] = 0.f;

    for (int ci0 = 0; ci0 < CI; ci0 += CI_C) {
        if (ci0) __syncthreads();
        for (int i = tid; i < CI_C*4*34; i += 128) {
            int cc = i / 136;
            int r  = i % 136;
            int yy = r / 34;
            int xx = r % 34;
            int gy = ty + yy - 1;
            int gx = tx + xx - 1;
            float v = 0.f;
            if (gy >= 0 && gy < H && gx >= 0 && gx < W)
                v = inb[((size_t)(ci0+cc))*HW + gy*W + gx];
            s_in[(cc*4 + yy)*RISTR + xx] = v;
        }
        for (int i = tid; i < CI_C*9*16; i += 128) {
            int cc = i / 144;
            int r  = i % 144;
            s_w[i] = g_wtr[((size_t)(ci0+cc))*144 + r];
        }
        __syncthreads();

#pragma unroll 1
        for (int cc = 0; cc < CI_C; cc++) {
#pragma unroll
            for (int ky = 0; ky < 3; ky++) {
                const float* rowp = &s_in[(cc*4 + py + ky)*RISTR];
#pragma unroll
                for (int kx = 0; kx < 3; kx++) {
                    float2 w2 = *(const float2*)&s_w[(cc*9 + ky*3 + kx)*16 + cog*2];
#pragma unroll
                    for (int m = 0; m < 4; m++) {
                        float v = rowp[px + 8*m + kx];
                        acc[0][m] += v * w2.x;
                        acc[1][m] += v * w2.y;
                    }
                }
            }
        }
    }

    int y = ty + py;
    size_t abase = lvlAOff(l) + (size_t)img*lvlN(l);
#pragma unroll
    for (int m = 0; m < 4; m++) {
        int x = tx + px + 8*m;
        if (x >= W) continue;
#pragma unroll
        for (int a = 0; a < 2; a++) {
            int co = cog*2 + a;
            if (co >= 15) break;
            float vv = acc[a][m];
            if (co < 3) {
                g_score[abase + ((size_t)y*W + x)*3 + co] = 1.f/(1.f + expf(-vv));
            } else {
                int cr = co - 3;
                g_loc[(abase + ((size_t)y*W + x)*3 + (cr>>2))*4 + (cr&3)] = vv;
            }
        }
    }
}

// ---------------- decode boxes + validity + sort keys (all levels) ----------
__global__ void decode_k(const float* __restrict__ anch0, const float* __restrict__ anch1,
                         const float* __restrict__ anch2)
{
    int gid = blockIdx.x*256 + threadIdx.x;
    if (gid >= ATOT) return;
    int l, r;
    const float* anchors;
    if (gid < AOFF1)      { l = 0; r = gid;         anchors = anch0; }
    else if (gid < AOFF2) { l = 1; r = gid - AOFF1; anchors = anch1; }
    else                  { l = 2; r = gid - AOFF2; anchors = anch2; }
    int N = lvlN(l);
    int a = r % N;
    float stride = (float)lvlStride(l);

    float sc = g_score[gid];
    float t0 = g_loc[(size_t)gid*4 + 0];
    float t1 = g_loc[(size_t)gid*4 + 1];
    float t2 = g_loc[(size_t)gid*4 + 2];
    float t3 = g_loc[(size_t)gid*4 + 3];
    float a0 = anchors[(size_t)a*4+0], a1 = anchors[(size_t)a*4+1];
    float a2 = anchors[(size_t)a*4+2], a3 = anchors[(size_t)a*4+3];
    float aw = a2 - a0, ah = a3 - a1;
    float x1 = a0 + t0*aw;
    float y1 = a1 + t1*ah;
    float x2 = x1 + aw*expf(t2);
    float y2 = y1 + ah*expf(t3);
    x1 = fminf(fmaxf(x1, 0.f), 512.f);
    y1 = fminf(fmaxf(y1, 0.f), 512.f);
    x2 = fminf(fmaxf(x2, 0.f), 512.f);
    y2 = fminf(fmaxf(y2, 0.f), 512.f);
    bool valid = (sc > 0.5f) && ((x2 - x1) >= 2.f*stride) && ((y2 - y1) >= 2.f*stride);
    float s = valid ? sc : -1.f;
    size_t o = (size_t)gid*4;
    g_boxes[o+0] = x1; g_boxes[o+1] = y1; g_boxes[o+2] = x2; g_boxes[o+3] = y2;
    g_sval[gid] = s;
    unsigned int u = __float_as_uint(s);
    u = (u & 0x80000000u) ? ~u : (u | 0x80000000u);
    g_keys[gid] = u;
}

// ---------------- exact top-256 via MSB radix select ----------------
__global__ void topk_k()
{
    __shared__ unsigned int hist[256];
    __shared__ unsigned long long lst[256];
    __shared__ unsigned int wsum[32];
    __shared__ unsigned int sPrefix;
    __shared__ int sK, sCGT, sCnt, sTot, sDone;

    int blk = blockIdx.x;
    int l = blk >> 1;
    int b = blk & 1;
    int N = lvlN(l);
    const unsigned int* keys = g_keys + lvlAOff(l) + (size_t)b*N;
    int tid = threadIdx.x;

    if (tid == 0) { sPrefix = 0u; sK = 256; sCGT = 0; sCnt = 0; sDone = 0; }
    __syncthreads();

    for (int byte = 3; byte >= 0; byte--) {
        for (int i = tid; i < 256; i += 1024) hist[i] = 0u;
        __syncthreads();
        unsigned int pf = sPrefix;
        unsigned int mask = (byte == 3) ? 0u : (0xFFFFFFFFu << ((byte+1)*8));
        for (int i = tid; i < N; i += 1024) {
            unsigned int k = keys[i];
            if ((k & mask) == pf) atomicAdd(&hist[(k >> (byte*8)) & 255], 1u);
        }
        __syncthreads();
        if (tid == 0) {
            int cum = 0;
            int kk = sK;
            int v = 255;
            for (; v >= 0; v--) {
                int c = (int)hist[v];
                if (cum + c >= kk) break;
                cum += c;
            }
            sPrefix |= ((unsigned int)v) << (byte*8);
            sK = kk - cum;
            sCGT += cum;
        }
        __syncthreads();
    }

    unsigned int T = sPrefix;
    int need = sK;
    int cg = sCGT;

    for (int i = tid; i < N; i += 1024) {
        unsigned int k = keys[i];
        if (k > T) {
            int p = atomicAdd(&sCnt, 1);
            lst[p] = ((unsigned long long)k << 32) | (unsigned int)(0xFFFFFFFFu - i);
        }
    }
    __syncthreads();
    if (tid < 256 && tid >= cg) lst[tid] = 0ull;
    __syncthreads();

    for (int k = 2; k <= 256; k <<= 1) {
        for (int j = k >> 1; j > 0; j >>= 1) {
            if (tid < 256) {
                int ixj = tid ^ j;
                if (ixj > tid) {
                    bool desc = ((tid & k) == 0);
                    unsigned long long A = lst[tid], Bv = lst[ixj];
                    bool sw = desc ? (A < Bv) : (A > Bv);
                    if (sw) { lst[tid] = Bv; lst[ixj] = A; }
                }
            }
            __syncthreads();
        }
    }

    if (tid < cg)
        g_topk[blk*256 + tid] = (int)(0xFFFFFFFFu - (unsigned int)(lst[tid] & 0xFFFFFFFFull));

    for (int base = 0; base < N; base += 1024) {
        __syncthreads();
        if (sDone >= need) break;
        int i = base + tid;
        int flag = (i < N) && (keys[i] == T);
        unsigned int m = __ballot_sync(0xffffffffu, flag);
        int lane = tid & 31, wd = tid >> 5;
        int laneoff = __popc(m & ((1u << lane) - 1u));
        if (lane == 0) wsum[wd] = __popc(m);
        __syncthreads();
        if (tid == 0) {
            int run = 0;
            for (int w = 0; w < 32; w++) { int c = (int)wsum[w]; wsum[w] = run; run += c; }
            sTot = run;
        }
        __syncthreads();
        if (flag) {
            int pos = sDone + (int)wsum[wd] + laneoff;
            if (pos < need) g_topk[blk*256 + cg + pos] = i;
        }
        __syncthreads();
        if (tid == 0) sDone += sTot;
    }
}

// ---------------- greedy NMS + ordering + dets/mask/coords ------------------
__global__ void nms_k(float* __restrict__ dout)
{
    __shared__ float bxs[256][4];
    __shared__ float varea[256];
    __shared__ float vvs[256];
    __shared__ int keep[256];
    __shared__ int ord[32];
    int blk = blockIdx.x;
    int lvl = blk >> 1;
    int b = blk & 1;
    int N = lvlN(lvl);
    int stride = lvlStride(lvl);
    size_t abase = lvlAOff(lvl) + (size_t)b*N;
    int j = threadIdx.x;
    int idx = g_topk[blk*256 + j];
    float x1 = g_boxes[(abase + idx)*4 + 0];
    float y1 = g_boxes[(abase + idx)*4 + 1];
    float x2 = g_boxes[(abase + idx)*4 + 2];
    float y2 = g_boxes[(abase + idx)*4 + 3];
    float v  = g_sval[abase + idx];
    bxs[j][0] = x1; bxs[j][1] = y1; bxs[j][2] = x2; bxs[j][3] = y2;
    vvs[j] = v;
    float areaj = (x2 - x1 + 1.f)*(y2 - y1 + 1.f);
    varea[j] = areaj;
    keep[j] = (v > 0.5f) ? 1 : 0;
    __syncthreads();
    for (int i = 0; i < 255; i++) {
        if (j > i && keep[i] && keep[j]) {
            float xx1 = fmaxf(bxs[i][0], x1);
            float yy1 = fmaxf(bxs[i][1], y1);
            float xx2 = fminf(bxs[i][2], x2);
            float yy2 = fminf(bxs[i][3], y2);
            float iw = fmaxf(0.f, xx2 - xx1 + 1.f);
            float ih = fmaxf(0.f, yy2 - yy1 + 1.f);
            float inter = iw*ih;
            float iou = inter / (varea[i] + areaj - inter);
            if (iou > 0.3f) keep[j] = 0;
        }
        __syncthreads();
    }
    if (j == 0) {
        int c = 0;
        for (int q = 0; q < 256 && c < 32; q++) if (keep[q]) ord[c++] = q;
        for (int q = 0; q < 256 && c < 32; q++) if (!keep[q]) ord[c++] = q;
    }
    __syncthreads();
    if (j < 32) {
        int o = ord[j];
        int m = keep[o];
        int slot = (b*3 + lvl)*32 + j;
        size_t dbase = (size_t)slot*5;
        if (m) {
            dout[dbase+0] = bxs[o][0];
            dout[dbase+1] = bxs[o][1];
            dout[dbase+2] = bxs[o][2];
            dout[dbase+3] = bxs[o][3];
            dout[dbase+4] = vvs[o];
        } else {
            dout[dbase+0] = 0.f; dout[dbase+1] = 0.f; dout[dbase+2] = 0.f;
            dout[dbase+3] = 0.f; dout[dbase+4] = 0.f;
        }
        dout[960 + slot] = m ? 1.f : 0.f;
        if (m) {
            g_coords[slot*4+0] = ((int)bxs[o][0]) / stride;
            g_coords[slot*4+1] = ((int)bxs[o][1]) / stride;
            g_coords[slot*4+2] = ((int)bxs[o][2]) / stride;
            g_coords[slot*4+3] = ((int)bxs[o][3]) / stride;
        } else {
            g_coords[slot*4+0] = 0; g_coords[slot*4+1] = 0;
            g_coords[slot*4+2] = 2; g_coords[slot*4+3] = 2;
        }
        g_mflag[slot] = m;
    }
}

// ---------------- ROI adaptive 7x7 max pool ----------------
__global__ void roipool_k(float* __restrict__ dout)
{
    int s = blockIdx.x;
    int b = blockIdx.y;
    int lvl = blockIdx.z;
    int c = threadIdx.x;
    int H = lvlH(lvl), W = lvlW(lvl);
    int slot = (b*3 + lvl)*32 + s;
    float* dst = dout + 1152 + ((size_t)slot*256 + c)*49;
    int m = g_mflag[slot];
    if (!m) {
#pragma unroll
        for (int k = 0; k < 49; k++) dst[k] = 0.f;
        return;
    }
    int x1 = g_coords[slot*4+0];
    int y1 = g_coords[slot*4+1];
    int x2 = g_coords[slot*4+2];
    int y2 = g_coords[slot*4+3];
    int Lx = x2 - x1;
    int Ly = y2 - y1;
    const float* f = g_f + lvlTOff(lvl) + ((size_t)b*256 + c)*H*W;
    for (int i = 0; i < 7; i++) {
        int ys = y1 + (i*Ly)/7;
        int ye = y1 + ((i+1)*Ly + 6)/7;
        for (int jx = 0; jx < 7; jx++) {
            int xs = x1 + (jx*Lx)/7;
            int xe = x1 + ((jx+1)*Lx + 6)/7;
            float mx = -3.402823466e38f;
            for (int y = ys; y < ye; y++)
                for (int x = xs; x < xe; x++)
                    mx = fmaxf(mx, f[y*W + x]);
            dst[i*7 + jx] = mx;
        }
    }
}

// ---------------- host orchestration (kernel launches ONLY) ----------------
#define CONVMMA_SMEM 59392

extern "C" void kernel_launch(void* const* d_in, const int* in_sizes, int n_in,
                              void* d_out, int out_size)
{
    const float* layer2   = (const float*)d_in[0];
    const float* layer3   = (const float*)d_in[1];
    const float* layer4   = (const float*)d_in[2];
    const float* anchors2 = (const float*)d_in[3];
    const float* anchors3 = (const float*)d_in[4];
    const float* anchors4 = (const float*)d_in[5];
    const float* hw1 = (const float*)d_in[6];
    const float* hg1 = (const float*)d_in[7];
    const float* hb1 = (const float*)d_in[8];
    const float* hm1 = (const float*)d_in[9];
    const float* hv1 = (const float*)d_in[10];
    const float* hw2 = (const float*)d_in[11];
    const float* hg2 = (const float*)d_in[12];
    const float* hb2 = (const float*)d_in[13];
    const float* hm2 = (const float*)d_in[14];
    const float* hv2 = (const float*)d_in[15];
    const float* clsw = (const float*)d_in[16];
    const float* locw = (const float*)d_in[17];
    float* out = (float*)d_out;

    cudaFuncSetAttribute(convmma_k, cudaFuncAttributeMaxDynamicSharedMemorySize,
                         CONVMMA_SMEM);

    wtrans_head_k<<<(256*9*128 + 255)/256, 256>>>(hw1, hg1, hb1, hm1, hv1, 0);
    wtrans_head_k<<<(256*9*128 + 255)/256, 256>>>(hw2, hg2, hb2, hm2, hv2, 1);
    wtrans_rpn_k<<<(256*9*16 + 255)/256, 256>>>(clsw, locw);

    upadd_k<<<(2*256*32*32 + 255)/256, 256>>>(layer3, layer4, -1, 0, 32, 32);
    upadd_k<<<(2*256*64*64 + 255)/256, 256>>>(layer2, nullptr, 0, 1, 64, 64);

    split_k<<<(TTOT/2 + 255)/256, 256>>>(layer4, 0);
    convmma_k<<<336, 256, CONVMMA_SMEM>>>(0);
    split_k<<<(TTOT/2 + 255)/256, 256>>>(nullptr, 1);
    convmma_k<<<336, 256, CONVMMA_SMEM>>>(1);

    conv_rpn_k<<<176, 128>>>();

    decode_k<<<(ATOT + 255)/256, 256>>>(anchors2, anchors3, anchors4);
    topk_k<<<6, 1024>>>();
    nms_k<<<6, 256>>>(out);
    roipool_k<<<dim3(32, 2, 3), 256>>>(out);
}